// round 11
// baseline (speedup 1.0000x reference)
#include <cuda_runtime.h>
#include <cuda_bf16.h>
#include <cuda_fp16.h>
#include <math.h>
#include <stdint.h>

// Problem constants
#define BATCH   2
#define SEQ     2048
#define EMB     1024
#define NHEAD   16
#define QKVN    3072
#define MROWS   4096
#define TINY_F  1.17549435e-38f
#define SCALE_Q 0.125f
#define LOG2E   1.4426950408889634f
#define BIGNEG2 -1.3e16f
#define BIGPOS2  1.3e16f

// Global scratch
__device__ __nv_bfloat16 g_x_hi[(size_t)MROWS * EMB];
__device__ __nv_bfloat16 g_x_lo[(size_t)MROWS * EMB];
__device__ __nv_bfloat16 g_w_hi[(size_t)EMB * QKVN];
__device__ __nv_bfloat16 g_w_lo[(size_t)EMB * QKVN];
__device__ __nv_bfloat16 g_qkv_hi[(size_t)MROWS * QKVN];
__device__ __nv_bfloat16 g_qkv_lo[(size_t)MROWS * QKVN];
__device__ __half        g_v[(size_t)MROWS * EMB];      // V fp16, [row][h*64+d]
__device__ float g_wsc[BATCH * SEQ];
__device__ float g_wvl[BATCH * SEQ];

// ---------------------------------------------------------------------------
// PTX helpers
// ---------------------------------------------------------------------------
#define MMA_BF16(c, a0, a1, a2, a3, b0, b1)                                  \
    asm volatile(                                                            \
        "mma.sync.aligned.m16n8k16.row.col.f32.bf16.bf16.f32 "               \
        "{%0,%1,%2,%3}, {%4,%5,%6,%7}, {%8,%9}, {%0,%1,%2,%3};"              \
        : "+f"((c)[0]), "+f"((c)[1]), "+f"((c)[2]), "+f"((c)[3])             \
        : "r"(a0), "r"(a1), "r"(a2), "r"(a3), "r"(b0), "r"(b1))

#define MMA_FP16(c, a0, a1, a2, a3, b0, b1)                                  \
    asm volatile(                                                            \
        "mma.sync.aligned.m16n8k16.row.col.f32.f16.f16.f32 "                 \
        "{%0,%1,%2,%3}, {%4,%5,%6,%7}, {%8,%9}, {%0,%1,%2,%3};"              \
        : "+f"((c)[0]), "+f"((c)[1]), "+f"((c)[2]), "+f"((c)[3])             \
        : "r"(a0), "r"(a1), "r"(a2), "r"(a3), "r"(b0), "r"(b1))

#define LDSM_X4(r0, r1, r2, r3, a)                                           \
    asm volatile("ldmatrix.sync.aligned.m8n8.x4.shared.b16 {%0,%1,%2,%3}, [%4];" \
        : "=r"(r0), "=r"(r1), "=r"(r2), "=r"(r3) : "r"(a))

#define LDSM_X4_T(r0, r1, r2, r3, a)                                         \
    asm volatile("ldmatrix.sync.aligned.m8n8.x4.trans.shared.b16 {%0,%1,%2,%3}, [%4];" \
        : "=r"(r0), "=r"(r1), "=r"(r2), "=r"(r3) : "r"(a))

#define CPA16(dst_u32, src_ptr)                                              \
    asm volatile("cp.async.cg.shared.global [%0], [%1], 16;"                 \
                 :: "r"(dst_u32), "l"(src_ptr))
#define CPA_COMMIT() asm volatile("cp.async.commit_group;")
#define CPA_WAIT1()  asm volatile("cp.async.wait_group 1;")
#define CPA_WAIT0()  asm volatile("cp.async.wait_group 0;")

__device__ __forceinline__ void split2(float x, float y,
                                       uint32_t& hi, uint32_t& lo)
{
    __nv_bfloat162 h = __floats2bfloat162_rn(x, y);
    float rx = x - __bfloat162float(h.x);
    float ry = y - __bfloat162float(h.y);
    __nv_bfloat162 l = __floats2bfloat162_rn(rx, ry);
    hi = *reinterpret_cast<uint32_t*>(&h);
    lo = *reinterpret_cast<uint32_t*>(&l);
}

__device__ __forceinline__ uint32_t packh2(float x, float y)
{
    __half2 h = __floats2half2_rn(x, y);
    return *reinterpret_cast<uint32_t*>(&h);
}

// ---------------------------------------------------------------------------
// Prep kernels
// ---------------------------------------------------------------------------
__device__ __forceinline__ void split_store(const float4* in, uint2* hi,
                                            uint2* lo, int i)
{
    float4 v = in[i];
    uint2 uh, ul;
    split2(v.x, v.y, uh.x, ul.x);
    split2(v.z, v.w, uh.y, ul.y);
    hi[i] = uh;
    lo[i] = ul;
}

__global__ void split_x_kernel(const float4* __restrict__ in)
{
    int i = blockIdx.x * blockDim.x + threadIdx.x;
    if (i < MROWS * EMB / 4)
        split_store(in, (uint2*)g_x_hi, (uint2*)g_x_lo, i);
}

__global__ void split_w_kernel(const float4* __restrict__ in)
{
    int i = blockIdx.x * blockDim.x + threadIdx.x;
    if (i < EMB * QKVN / 4)
        split_store(in, (uint2*)g_w_hi, (uint2*)g_w_lo, i);
}

__global__ void wprep_kernel(const float* __restrict__ w)
{
    int i = blockIdx.x * blockDim.x + threadIdx.x;
    if (i < BATCH * SEQ) {
        const float v = w[i];
        const bool z = (v == 0.0f), on = (v == 1.0f);
        g_wsc[i] = (z || on) ? 0.0f : SCALE_Q * LOG2E;
        g_wvl[i] = z ? BIGNEG2 : (on ? BIGPOS2 : log2f(v + TINY_F));
    }
}

// ---------------------------------------------------------------------------
// Kernel 1: qkv = x @ W + b, bf16x3 mma. CTA 128x128, BK=32, 256 threads.
// 2-buffer ring, issue-before-wait. MMA issue order interleaves the four
// (mt, col) accumulators per term -> same-acc RAW distance 4 (asm volatile
// fixes source order as issue order; distance 1 was the 52%-tensor stall).
// ---------------------------------------------------------------------------
#define GA_STR 40
#define GB_STR 136
#define GA_H   (128 * GA_STR)
#define GB_H   (32 * GB_STR)
#define GBUF_H (2 * GA_H + 2 * GB_H)
#define GEMM_SMEM_BYTES (2 * GBUF_H * 2)  // 75776 -> 2 CTAs/SM

__global__ void __launch_bounds__(256)
qkv_gemm(const float* __restrict__ bias)
{
    extern __shared__ __nv_bfloat16 sh[];
    const uint32_t sbase = (uint32_t)__cvta_generic_to_shared(sh);

    const int tid  = threadIdx.x;
    const int lane = tid & 31, wid = tid >> 5;
    const int g = lane >> 2, tig = lane & 3;
    const int wr = wid >> 1, wc = wid & 1;
    const int bn = blockIdx.x * 128, bm = blockIdx.y * 128;

    const uint32_t OAh = 0, OAl = GA_H * 2;
    const uint32_t OBh = 2 * GA_H * 2, OBl = (2 * GA_H + GB_H) * 2;
    const uint32_t BUFB = GBUF_H * 2;

    float acc[2][8][4];
#pragma unroll
    for (int mt = 0; mt < 2; mt++)
#pragma unroll
        for (int j = 0; j < 8; j++)
#pragma unroll
            for (int q = 0; q < 4; q++) acc[mt][j][q] = 0.0f;

    const int a_row = (lane & 7) + 8 * ((lane >> 3) & 1);
    const int a_col = 8 * (lane >> 4);
    const int b_row = lane & 15;
    const int b_col = 8 * (lane >> 4);

#define GEMM_ISSUE(buf, kt)                                                  \
    do {                                                                     \
        const uint32_t sb = sbase + (buf) * BUFB;                            \
        _Pragma("unroll")                                                    \
        for (int i = 0; i < 2; i++) {                                        \
            int ch = tid + 256 * i;                                          \
            int r = ch >> 2, sg = ch & 3;                                    \
            size_t go = (size_t)(bm + r) * EMB + (kt) * 32 + sg * 8;         \
            uint32_t d = sb + (uint32_t)(r * GA_STR + sg * 8) * 2;           \
            CPA16(d + OAh, g_x_hi + go);                                     \
            CPA16(d + OAl, g_x_lo + go);                                     \
        }                                                                    \
        _Pragma("unroll")                                                    \
        for (int i = 0; i < 2; i++) {                                        \
            int ch = tid + 256 * i;                                          \
            int r = ch >> 4, sg = ch & 15;                                   \
            size_t go = (size_t)((kt) * 32 + r) * QKVN + bn + sg * 8;        \
            uint32_t d = sb + (uint32_t)(r * GB_STR + sg * 8) * 2;           \
            CPA16(d + OBh, g_w_hi + go);                                     \
            CPA16(d + OBl, g_w_lo + go);                                     \
        }                                                                    \
    } while (0)

    GEMM_ISSUE(0, 0);
    CPA_COMMIT();

    for (int kt = 0; kt < 32; kt++) {
        const int buf = kt & 1;
        if (kt < 31) {
            GEMM_ISSUE(buf ^ 1, kt + 1);
            CPA_COMMIT();
            CPA_WAIT1();
        } else {
            CPA_WAIT0();
        }
        __syncthreads();

        const uint32_t sb = sbase + buf * BUFB;
#pragma unroll
        for (int ks = 0; ks < 2; ks++) {
            const int k0 = ks * 16;
            uint32_t ah[2][4], al[2][4];
#pragma unroll
            for (int mt = 0; mt < 2; mt++) {
                const uint32_t off =
                    (uint32_t)((wr * 32 + mt * 16 + a_row) * GA_STR + k0 + a_col) * 2;
                LDSM_X4(ah[mt][0], ah[mt][1], ah[mt][2], ah[mt][3], sb + OAh + off);
                LDSM_X4(al[mt][0], al[mt][1], al[mt][2], al[mt][3], sb + OAl + off);
            }
#pragma unroll
            for (int jp = 0; jp < 4; jp++) {
                const uint32_t off =
                    (uint32_t)((k0 + b_row) * GB_STR + wc * 64 + jp * 16 + b_col) * 2;
                uint32_t bh0, bh1, bh2, bh3, bl0, bl1, bl2, bl3;
                LDSM_X4_T(bh0, bh1, bh2, bh3, sb + OBh + off);
                LDSM_X4_T(bl0, bl1, bl2, bl3, sb + OBl + off);
                // term hh: 4 independent accumulators
                MMA_BF16(acc[0][2 * jp],     ah[0][0], ah[0][1], ah[0][2], ah[0][3], bh0, bh1);
                MMA_BF16(acc[1][2 * jp],     ah[1][0], ah[1][1], ah[1][2], ah[1][3], bh0, bh1);
                MMA_BF16(acc[0][2 * jp + 1], ah[0][0], ah[0][1], ah[0][2], ah[0][3], bh2, bh3);
                MMA_BF16(acc[1][2 * jp + 1], ah[1][0], ah[1][1], ah[1][2], ah[1][3], bh2, bh3);
                // term hl
                MMA_BF16(acc[0][2 * jp],     ah[0][0], ah[0][1], ah[0][2], ah[0][3], bl0, bl1);
                MMA_BF16(acc[1][2 * jp],     ah[1][0], ah[1][1], ah[1][2], ah[1][3], bl0, bl1);
                MMA_BF16(acc[0][2 * jp + 1], ah[0][0], ah[0][1], ah[0][2], ah[0][3], bl2, bl3);
                MMA_BF16(acc[1][2 * jp + 1], ah[1][0], ah[1][1], ah[1][2], ah[1][3], bl2, bl3);
                // term lh
                MMA_BF16(acc[0][2 * jp],     al[0][0], al[0][1], al[0][2], al[0][3], bh0, bh1);
                MMA_BF16(acc[1][2 * jp],     al[1][0], al[1][1], al[1][2], al[1][3], bh0, bh1);
                MMA_BF16(acc[0][2 * jp + 1], al[0][0], al[0][1], al[0][2], al[0][3], bh2, bh3);
                MMA_BF16(acc[1][2 * jp + 1], al[1][0], al[1][1], al[1][2], al[1][3], bh2, bh3);
            }
        }
        __syncthreads();
    }

    // Epilogue: hi/lo bf16 everywhere; fp16 V for per-head v-region columns.
#pragma unroll
    for (int mt = 0; mt < 2; mt++) {
        const int row0 = bm + wr * 32 + mt * 16 + g;
#pragma unroll
        for (int j = 0; j < 8; j++) {
            const int col = bn + wc * 64 + j * 8 + 2 * tig;
            const float2 bb = *(const float2*)(bias + col);
            const float v00 = acc[mt][j][0] + bb.x, v01 = acc[mt][j][1] + bb.y;
            const float v10 = acc[mt][j][2] + bb.x, v11 = acc[mt][j][3] + bb.y;
            uint32_t h0, l0, h1, l1;
            split2(v00, v01, h0, l0);
            split2(v10, v11, h1, l1);
            *(uint32_t*)(g_qkv_hi + (size_t)row0 * QKVN + col)       = h0;
            *(uint32_t*)(g_qkv_lo + (size_t)row0 * QKVN + col)       = l0;
            *(uint32_t*)(g_qkv_hi + (size_t)(row0 + 8) * QKVN + col) = h1;
            *(uint32_t*)(g_qkv_lo + (size_t)(row0 + 8) * QKVN + col) = l1;
            // qkv row layout: per-head [q(64) | k(64) | v(64)] blocks of 192.
            const int cm = col % 192;
            if (cm >= 128) {
                const int head = col / 192;
                const int vc = head * 64 + (cm - 128);
                *(uint32_t*)(g_v + (size_t)row0 * EMB + vc)       = packh2(v00, v01);
                *(uint32_t*)(g_v + (size_t)(row0 + 8) * EMB + vc) = packh2(v10, v11);
            }
        }
    }
#undef GEMM_ISSUE
}

// ---------------------------------------------------------------------------
// Kernel 2: flash attention. Grid (S/128, H, B), 256 threads, 2 CTAs/SM.
// S = QK^T bf16x3 (same-acc distance 2 issue order); PV single-term fp16.
// BQ=128, BN=64, 2-slot KV ring, exp2 softmax.
// ---------------------------------------------------------------------------
#define ATS      72
#define QTILE_B  (128 * ATS * 2)
#define KT64_B   (64 * ATS * 2)
#define BQh      0
#define BQl      QTILE_B
#define KVBASE   (2 * QTILE_B)
#define SLOT_B   (3 * KT64_B)                  // Khi, Klo, V
#define OKh      0
#define OKl      KT64_B
#define OV       (2 * KT64_B)
#define ATTN_SMEM_BYTES (KVBASE + 2 * SLOT_B)  // 92160 -> 2 CTAs/SM
#define NKT      (SEQ / 64)                    // 32

__global__ void __launch_bounds__(256, 2)
attn_bf16(float* __restrict__ out)
{
    extern __shared__ char shb[];
    const uint32_t sb = (uint32_t)__cvta_generic_to_shared(shb);

    const int tid  = threadIdx.x;
    const int lane = tid & 31, wrp = tid >> 5;
    const int g = lane >> 2, tig = lane & 3;
    const int qt = blockIdx.x, h = blockIdx.y, b = blockIdx.z;

    const int a_row = (lane & 7) + 8 * ((lane >> 3) & 1);
    const int a_col = 8 * (lane >> 4);
    const int k_row = (lane & 7) + 8 * (lane >> 4);
    const int k_col = 8 * ((lane >> 3) & 1);

#define KV_ISSUE(slot, tt)                                                   \
    do {                                                                     \
        const uint32_t kbase = sb + KVBASE + (uint32_t)(slot) * SLOT_B;      \
        _Pragma("unroll")                                                    \
        for (int i = 0; i < 2; i++) {                                        \
            int ch = tid + 256 * i;                                          \
            int r = ch >> 3, sg = ch & 7;                                    \
            size_t gk = (size_t)(b * SEQ + (tt) * 64 + r) * QKVN + h * 192 + 64 + sg * 8; \
            size_t gv = (size_t)(b * SEQ + (tt) * 64 + r) * EMB + h * 64 + sg * 8; \
            uint32_t d = (uint32_t)(r * ATS + sg * 8) * 2;                   \
            CPA16(kbase + OKh + d, g_qkv_hi + gk);                           \
            CPA16(kbase + OKl + d, g_qkv_lo + gk);                           \
            CPA16(kbase + OV  + d, g_v + gv);                                \
        }                                                                    \
        CPA_COMMIT();                                                        \
    } while (0)

    // ---- prologue: Q (group 0), KV tile 0 (group 1) ----
#pragma unroll
    for (int i = 0; i < 4; i++) {
        const int ch = tid + 256 * i;
        const int r = ch >> 3, sg = ch & 7;
        const size_t go = (size_t)(b * SEQ + qt * 128 + r) * QKVN + h * 192 + sg * 8;
        const uint32_t d = (uint32_t)(r * ATS + sg * 8) * 2;
        CPA16(sb + BQh + d, g_qkv_hi + go);
        CPA16(sb + BQl + d, g_qkv_lo + go);
    }
    CPA_COMMIT();
    KV_ISSUE(0, 0);
    CPA_WAIT1();           // Q landed
    __syncthreads();

    // Q-hi fragments -> registers; Q-lo reloaded per tile
    uint32_t qh[4][4];
#pragma unroll
    for (int kk = 0; kk < 4; kk++) {
        const uint32_t off =
            (uint32_t)((16 * wrp + a_row) * ATS + kk * 16 + a_col) * 2;
        LDSM_X4(qh[kk][0], qh[kk][1], qh[kk][2], qh[kk][3], sb + BQh + off);
    }

    float m0 = -1e30f, m1 = -1e30f, l0 = 0.0f, l1 = 0.0f;
    float o[8][4];
#pragma unroll
    for (int j = 0; j < 8; j++)
        o[j][0] = o[j][1] = o[j][2] = o[j][3] = 0.0f;

    const float* wscp = g_wsc + b * SEQ;
    const float* wvlp = g_wvl + b * SEQ;

    for (int t = 0; t < NKT; t++) {
        const int slot = t & 1;
        CPA_WAIT0();
        __syncthreads();

        if (t + 1 < NKT)
            KV_ISSUE(slot ^ 1, t + 1);

        const uint32_t kb = sb + KVBASE + (uint32_t)slot * SLOT_B;

        // ---- S = Q K^T : 16 q-rows x 64 keys per warp (bf16x3) ----
        float s[8][4];
#pragma unroll
        for (int j = 0; j < 8; j++)
            s[j][0] = s[j][1] = s[j][2] = s[j][3] = 0.0f;

#pragma unroll
        for (int kk = 0; kk < 4; kk++) {
            uint32_t ql0, ql1, ql2, ql3;
            const uint32_t qoff =
                (uint32_t)((16 * wrp + a_row) * ATS + kk * 16 + a_col) * 2;
            LDSM_X4(ql0, ql1, ql2, ql3, sb + BQl + qoff);
#pragma unroll
            for (int jp = 0; jp < 4; jp++) {
                const uint32_t off =
                    (uint32_t)((jp * 16 + k_row) * ATS + kk * 16 + k_col) * 2;
                uint32_t kh0, kh1, kh2, kh3, kl0, kl1, kl2, kl3;
                LDSM_X4(kh0, kh1, kh2, kh3, kb + OKh + off);
                LDSM_X4(kl0, kl1, kl2, kl3, kb + OKl + off);
                // same-acc distance 2 issue order
                MMA_BF16(s[2 * jp],     qh[kk][0], qh[kk][1], qh[kk][2], qh[kk][3], kh0, kh1);
                MMA_BF16(s[2 * jp + 1], qh[kk][0], qh[kk][1], qh[kk][2], qh[kk][3], kh2, kh3);
                MMA_BF16(s[2 * jp],     qh[kk][0], qh[kk][1], qh[kk][2], qh[kk][3], kl0, kl1);
                MMA_BF16(s[2 * jp + 1], qh[kk][0], qh[kk][1], qh[kk][2], qh[kk][3], kl2, kl3);
                MMA_BF16(s[2 * jp],     ql0, ql1, ql2, ql3, kh0, kh1);
                MMA_BF16(s[2 * jp + 1], ql0, ql1, ql2, ql3, kh2, kh3);
            }
        }

        // ---- logit transform (log2 domain) + row max ----
        const int wbase = t * 64;
        float mx0 = -1e30f, mx1 = -1e30f;
#pragma unroll
        for (int j = 0; j < 8; j++) {
            const float2 ws = *(const float2*)&wscp[wbase + j * 8 + 2 * tig];
            const float2 wv = *(const float2*)&wvlp[wbase + j * 8 + 2 * tig];
            s[j][0] = fmaf(s[j][0], ws.x, wv.x);
            s[j][1] = fmaf(s[j][1], ws.y, wv.y);
            s[j][2] = fmaf(s[j][2], ws.x, wv.x);
            s[j][3] = fmaf(s[j][3], ws.y, wv.y);
            mx0 = fmaxf(mx0, fmaxf(s[j][0], s[j][1]));
            mx1 = fmaxf(mx1, fmaxf(s[j][2], s[j][3]));
        }
        mx0 = fmaxf(mx0, __shfl_xor_sync(0xffffffffu, mx0, 1));
        mx0 = fmaxf(mx0, __shfl_xor_sync(0xffffffffu, mx0, 2));
        mx1 = fmaxf(mx1, __shfl_xor_sync(0xffffffffu, mx1, 1));
        mx1 = fmaxf(mx1, __shfl_xor_sync(0xffffffffu, mx1, 2));

        const float mn0 = fmaxf(m0, mx0), mn1 = fmaxf(m1, mx1);
        const float c0 = exp2f(m0 - mn0), c1 = exp2f(m1 - mn1);
        m0 = mn0; m1 = mn1;

        float rs0 = 0.0f, rs1 = 0.0f;
#pragma unroll
        for (int j = 0; j < 8; j++) {
            s[j][0] = exp2f(s[j][0] - m0);
            s[j][1] = exp2f(s[j][1] - m0);
            s[j][2] = exp2f(s[j][2] - m1);
            s[j][3] = exp2f(s[j][3] - m1);
            rs0 += s[j][0] + s[j][1];
            rs1 += s[j][2] + s[j][3];
        }
        rs0 += __shfl_xor_sync(0xffffffffu, rs0, 1);
        rs0 += __shfl_xor_sync(0xffffffffu, rs0, 2);
        rs1 += __shfl_xor_sync(0xffffffffu, rs1, 1);
        rs1 += __shfl_xor_sync(0xffffffffu, rs1, 2);

        l0 = l0 * c0 + rs0;
        l1 = l1 * c1 + rs1;
#pragma unroll
        for (int j = 0; j < 8; j++) {
            o[j][0] *= c0; o[j][1] *= c0;
            o[j][2] *= c1; o[j][3] *= c1;
        }

        // ---- O += P V : single-term fp16 ----
#pragma unroll
        for (int kk = 0; kk < 4; kk++) {
            uint32_t ph[4];
            ph[0] = packh2(s[2 * kk][0],     s[2 * kk][1]);
            ph[1] = packh2(s[2 * kk][2],     s[2 * kk][3]);
            ph[2] = packh2(s[2 * kk + 1][0], s[2 * kk + 1][1]);
            ph[3] = packh2(s[2 * kk + 1][2], s[2 * kk + 1][3]);
#pragma unroll
            for (int jp = 0; jp < 4; jp++) {
                const uint32_t off =
                    (uint32_t)((kk * 16 + a_row) * ATS + jp * 16 + a_col) * 2;
                uint32_t vh0, vh1, vh2, vh3;
                LDSM_X4_T(vh0, vh1, vh2, vh3, kb + OV + off);
                MMA_FP16(o[2 * jp],     ph[0], ph[1], ph[2], ph[3], vh0, vh1);
                MMA_FP16(o[2 * jp + 1], ph[0], ph[1], ph[2], ph[3], vh2, vh3);
            }
        }
    }

    // ---- epilogue ----
    const float i0 = 1.0f / l0, i1 = 1.0f / l1;
    const int grow = b * SEQ + qt * 128 + 16 * wrp + g;
#pragma unroll
    for (int j = 0; j < 8; j++) {
        const int col = h * 64 + j * 8 + 2 * tig;
        *(float2*)(out + (size_t)grow * EMB + col) =
            make_float2(o[j][0] * i0, o[j][1] * i0);
        *(float2*)(out + (size_t)(grow + 8) * EMB + col) =
            make_float2(o[j][2] * i1, o[j][3] * i1);
    }
#undef KV_ISSUE
}

// ---------------------------------------------------------------------------
extern "C" void kernel_launch(void* const* d_in, const int* in_sizes, int n_in,
                              void* d_out, int out_size)
{
    const float* x    = (const float*)d_in[0];
    const float* w    = (const float*)d_in[1];
    const float* Wqkv = (const float*)d_in[2];
    const float* bqkv = (const float*)d_in[3];
    float* out = (float*)d_out;

    cudaFuncSetAttribute(qkv_gemm,
                         cudaFuncAttributeMaxDynamicSharedMemorySize,
                         GEMM_SMEM_BYTES);
    cudaFuncSetAttribute(attn_bf16,
                         cudaFuncAttributeMaxDynamicSharedMemorySize,
                         ATTN_SMEM_BYTES);

    split_x_kernel<<<MROWS * EMB / 4 / 256, 256>>>((const float4*)x);
    split_w_kernel<<<EMB * QKVN / 4 / 256, 256>>>((const float4*)Wqkv);
    wprep_kernel<<<(BATCH * SEQ + 255) / 256, 256>>>(w);

    dim3 g1(QKVN / 128, MROWS / 128);            // (24, 32)
    qkv_gemm<<<g1, 256, GEMM_SMEM_BYTES>>>(bqkv);

    dim3 g2(SEQ / 128, NHEAD, BATCH);            // (16, 16, 2)
    attn_bf16<<<g2, 256, ATTN_SMEM_BYTES>>>(out);
}

// round 12
// speedup vs baseline: 1.0707x; 1.0707x over previous
#include <cuda_runtime.h>
#include <cuda_bf16.h>
#include <cuda_fp16.h>
#include <math.h>
#include <stdint.h>

// Problem constants
#define BATCH   2
#define SEQ     2048
#define EMB     1024
#define NHEAD   16
#define QKVN    3072
#define MROWS   4096
#define TINY_F  1.17549435e-38f
#define SCALE_Q 0.125f
#define LOG2E   1.4426950408889634f
#define BIGNEG2 -1.3e16f
#define BIGPOS2  1.3e16f

// Global scratch
__device__ __nv_bfloat16 g_x_hi[(size_t)MROWS * EMB];
__device__ __nv_bfloat16 g_x_lo[(size_t)MROWS * EMB];
__device__ __nv_bfloat16 g_w_hi[(size_t)EMB * QKVN];
__device__ __nv_bfloat16 g_w_lo[(size_t)EMB * QKVN];
__device__ __half g_q[(size_t)MROWS * EMB];      // Q fp16   [row][h*64+d]
__device__ __half g_k_hi[(size_t)MROWS * EMB];   // K fp16 hi
__device__ __half g_k_lo[(size_t)MROWS * EMB];   // K fp16 lo
__device__ __half g_v[(size_t)MROWS * EMB];      // V fp16
__device__ float g_wsc[BATCH * SEQ];             // log2-domain scale
__device__ float g_wvl[BATCH * SEQ];             // log2-domain bias

// ---------------------------------------------------------------------------
// PTX helpers
// ---------------------------------------------------------------------------
#define MMA_BF16(c, a0, a1, a2, a3, b0, b1)                                  \
    asm volatile(                                                            \
        "mma.sync.aligned.m16n8k16.row.col.f32.bf16.bf16.f32 "               \
        "{%0,%1,%2,%3}, {%4,%5,%6,%7}, {%8,%9}, {%0,%1,%2,%3};"              \
        : "+f"((c)[0]), "+f"((c)[1]), "+f"((c)[2]), "+f"((c)[3])             \
        : "r"(a0), "r"(a1), "r"(a2), "r"(a3), "r"(b0), "r"(b1))

#define MMA_FP16(c, a0, a1, a2, a3, b0, b1)                                  \
    asm volatile(                                                            \
        "mma.sync.aligned.m16n8k16.row.col.f32.f16.f16.f32 "                 \
        "{%0,%1,%2,%3}, {%4,%5,%6,%7}, {%8,%9}, {%0,%1,%2,%3};"              \
        : "+f"((c)[0]), "+f"((c)[1]), "+f"((c)[2]), "+f"((c)[3])             \
        : "r"(a0), "r"(a1), "r"(a2), "r"(a3), "r"(b0), "r"(b1))

#define LDSM_X4(r0, r1, r2, r3, a)                                           \
    asm volatile("ldmatrix.sync.aligned.m8n8.x4.shared.b16 {%0,%1,%2,%3}, [%4];" \
        : "=r"(r0), "=r"(r1), "=r"(r2), "=r"(r3) : "r"(a))

#define LDSM_X4_T(r0, r1, r2, r3, a)                                         \
    asm volatile("ldmatrix.sync.aligned.m8n8.x4.trans.shared.b16 {%0,%1,%2,%3}, [%4];" \
        : "=r"(r0), "=r"(r1), "=r"(r2), "=r"(r3) : "r"(a))

#define CPA16(dst_u32, src_ptr)                                              \
    asm volatile("cp.async.cg.shared.global [%0], [%1], 16;"                 \
                 :: "r"(dst_u32), "l"(src_ptr))
#define CPA_COMMIT() asm volatile("cp.async.commit_group;")
#define CPA_WAIT1()  asm volatile("cp.async.wait_group 1;")
#define CPA_WAIT0()  asm volatile("cp.async.wait_group 0;")

__device__ __forceinline__ void split2(float x, float y,
                                       uint32_t& hi, uint32_t& lo)
{
    __nv_bfloat162 h = __floats2bfloat162_rn(x, y);
    float rx = x - __bfloat162float(h.x);
    float ry = y - __bfloat162float(h.y);
    __nv_bfloat162 l = __floats2bfloat162_rn(rx, ry);
    hi = *reinterpret_cast<uint32_t*>(&h);
    lo = *reinterpret_cast<uint32_t*>(&l);
}

__device__ __forceinline__ uint32_t packh2(float x, float y)
{
    __half2 h = __floats2half2_rn(x, y);
    return *reinterpret_cast<uint32_t*>(&h);
}

__device__ __forceinline__ void split2h(float x, float y,
                                        uint32_t& hi, uint32_t& lo)
{
    __half2 h = __floats2half2_rn(x, y);
    float rx = x - __half2float(h.x);
    float ry = y - __half2float(h.y);
    __half2 l = __floats2half2_rn(rx, ry);
    hi = *reinterpret_cast<uint32_t*>(&h);
    lo = *reinterpret_cast<uint32_t*>(&l);
}

// ---------------------------------------------------------------------------
// Prep kernels
// ---------------------------------------------------------------------------
__device__ __forceinline__ void split_store(const float4* in, uint2* hi,
                                            uint2* lo, int i)
{
    float4 v = in[i];
    uint2 uh, ul;
    split2(v.x, v.y, uh.x, ul.x);
    split2(v.z, v.w, uh.y, ul.y);
    hi[i] = uh;
    lo[i] = ul;
}

__global__ void split_x_kernel(const float4* __restrict__ in)
{
    int i = blockIdx.x * blockDim.x + threadIdx.x;
    if (i < MROWS * EMB / 4)
        split_store(in, (uint2*)g_x_hi, (uint2*)g_x_lo, i);
}

__global__ void split_w_kernel(const float4* __restrict__ in)
{
    int i = blockIdx.x * blockDim.x + threadIdx.x;
    if (i < EMB * QKVN / 4)
        split_store(in, (uint2*)g_w_hi, (uint2*)g_w_lo, i);
}

__global__ void wprep_kernel(const float* __restrict__ w)
{
    int i = blockIdx.x * blockDim.x + threadIdx.x;
    if (i < BATCH * SEQ) {
        const float v = w[i];
        const bool z = (v == 0.0f), on = (v == 1.0f);
        g_wsc[i] = (z || on) ? 0.0f : SCALE_Q * LOG2E;
        g_wvl[i] = z ? BIGNEG2 : (on ? BIGPOS2 : log2f(v + TINY_F));
    }
}

// ---------------------------------------------------------------------------
// Kernel 1: qkv = x @ W + b, bf16x3 mma. CTA 128x128, BK=32, 256 threads.
// 2-buffer ring, issue-before-wait. Epilogue routes each column pair by
// per-head region (row layout: [q(64)|k(64)|v(64)] blocks of 192):
//   q -> g_q fp16; k -> g_k_hi/g_k_lo fp16 pair; v -> g_v fp16.
// ---------------------------------------------------------------------------
#define GA_STR 40
#define GB_STR 136
#define GA_H   (128 * GA_STR)
#define GB_H   (32 * GB_STR)
#define GBUF_H (2 * GA_H + 2 * GB_H)
#define GEMM_SMEM_BYTES (2 * GBUF_H * 2)  // 75776 -> 2 CTAs/SM

__global__ void __launch_bounds__(256)
qkv_gemm(const float* __restrict__ bias)
{
    extern __shared__ __nv_bfloat16 sh[];
    const uint32_t sbase = (uint32_t)__cvta_generic_to_shared(sh);

    const int tid  = threadIdx.x;
    const int lane = tid & 31, wid = tid >> 5;
    const int g = lane >> 2, tig = lane & 3;
    const int wr = wid >> 1, wc = wid & 1;
    const int bn = blockIdx.x * 128, bm = blockIdx.y * 128;

    const uint32_t OAh = 0, OAl = GA_H * 2;
    const uint32_t OBh = 2 * GA_H * 2, OBl = (2 * GA_H + GB_H) * 2;
    const uint32_t BUFB = GBUF_H * 2;

    float acc[2][8][4];
#pragma unroll
    for (int mt = 0; mt < 2; mt++)
#pragma unroll
        for (int j = 0; j < 8; j++)
#pragma unroll
            for (int q = 0; q < 4; q++) acc[mt][j][q] = 0.0f;

    const int a_row = (lane & 7) + 8 * ((lane >> 3) & 1);
    const int a_col = 8 * (lane >> 4);
    const int b_row = lane & 15;
    const int b_col = 8 * (lane >> 4);

#define GEMM_ISSUE(buf, kt)                                                  \
    do {                                                                     \
        const uint32_t sb = sbase + (buf) * BUFB;                            \
        _Pragma("unroll")                                                    \
        for (int i = 0; i < 2; i++) {                                        \
            int ch = tid + 256 * i;                                          \
            int r = ch >> 2, sg = ch & 3;                                    \
            size_t go = (size_t)(bm + r) * EMB + (kt) * 32 + sg * 8;         \
            uint32_t d = sb + (uint32_t)(r * GA_STR + sg * 8) * 2;           \
            CPA16(d + OAh, g_x_hi + go);                                     \
            CPA16(d + OAl, g_x_lo + go);                                     \
        }                                                                    \
        _Pragma("unroll")                                                    \
        for (int i = 0; i < 2; i++) {                                        \
            int ch = tid + 256 * i;                                          \
            int r = ch >> 4, sg = ch & 15;                                   \
            size_t go = (size_t)((kt) * 32 + r) * QKVN + bn + sg * 8;        \
            uint32_t d = sb + (uint32_t)(r * GB_STR + sg * 8) * 2;           \
            CPA16(d + OBh, g_w_hi + go);                                     \
            CPA16(d + OBl, g_w_lo + go);                                     \
        }                                                                    \
    } while (0)

    GEMM_ISSUE(0, 0);
    CPA_COMMIT();

    for (int kt = 0; kt < 32; kt++) {
        const int buf = kt & 1;
        if (kt < 31) {
            GEMM_ISSUE(buf ^ 1, kt + 1);
            CPA_COMMIT();
            CPA_WAIT1();
        } else {
            CPA_WAIT0();
        }
        __syncthreads();

        const uint32_t sb = sbase + buf * BUFB;
#pragma unroll
        for (int ks = 0; ks < 2; ks++) {
            const int k0 = ks * 16;
            uint32_t ah[2][4], al[2][4];
#pragma unroll
            for (int mt = 0; mt < 2; mt++) {
                const uint32_t off =
                    (uint32_t)((wr * 32 + mt * 16 + a_row) * GA_STR + k0 + a_col) * 2;
                LDSM_X4(ah[mt][0], ah[mt][1], ah[mt][2], ah[mt][3], sb + OAh + off);
                LDSM_X4(al[mt][0], al[mt][1], al[mt][2], al[mt][3], sb + OAl + off);
            }
#pragma unroll
            for (int jp = 0; jp < 4; jp++) {
                const uint32_t off =
                    (uint32_t)((k0 + b_row) * GB_STR + wc * 64 + jp * 16 + b_col) * 2;
                uint32_t bh0, bh1, bh2, bh3, bl0, bl1, bl2, bl3;
                LDSM_X4_T(bh0, bh1, bh2, bh3, sb + OBh + off);
                LDSM_X4_T(bl0, bl1, bl2, bl3, sb + OBl + off);
                MMA_BF16(acc[0][2 * jp],     ah[0][0], ah[0][1], ah[0][2], ah[0][3], bh0, bh1);
                MMA_BF16(acc[1][2 * jp],     ah[1][0], ah[1][1], ah[1][2], ah[1][3], bh0, bh1);
                MMA_BF16(acc[0][2 * jp + 1], ah[0][0], ah[0][1], ah[0][2], ah[0][3], bh2, bh3);
                MMA_BF16(acc[1][2 * jp + 1], ah[1][0], ah[1][1], ah[1][2], ah[1][3], bh2, bh3);
                MMA_BF16(acc[0][2 * jp],     ah[0][0], ah[0][1], ah[0][2], ah[0][3], bl0, bl1);
                MMA_BF16(acc[1][2 * jp],     ah[1][0], ah[1][1], ah[1][2], ah[1][3], bl0, bl1);
                MMA_BF16(acc[0][2 * jp + 1], ah[0][0], ah[0][1], ah[0][2], ah[0][3], bl2, bl3);
                MMA_BF16(acc[1][2 * jp + 1], ah[1][0], ah[1][1], ah[1][2], ah[1][3], bl2, bl3);
                MMA_BF16(acc[0][2 * jp],     al[0][0], al[0][1], al[0][2], al[0][3], bh0, bh1);
                MMA_BF16(acc[1][2 * jp],     al[1][0], al[1][1], al[1][2], al[1][3], bh0, bh1);
                MMA_BF16(acc[0][2 * jp + 1], al[0][0], al[0][1], al[0][2], al[0][3], bh2, bh3);
                MMA_BF16(acc[1][2 * jp + 1], al[1][0], al[1][1], al[1][2], al[1][3], bh2, bh3);
            }
        }
        __syncthreads();
    }

    // Epilogue: route column pairs into q / k(hi,lo) / v fp16 arrays.
    // col is even and 64-wide regions are even-aligned, so pairs never
    // straddle regions.
#pragma unroll
    for (int mt = 0; mt < 2; mt++) {
        const int row0 = bm + wr * 32 + mt * 16 + g;
#pragma unroll
        for (int j = 0; j < 8; j++) {
            const int col = bn + wc * 64 + j * 8 + 2 * tig;
            const float2 bb = *(const float2*)(bias + col);
            const float v00 = acc[mt][j][0] + bb.x, v01 = acc[mt][j][1] + bb.y;
            const float v10 = acc[mt][j][2] + bb.x, v11 = acc[mt][j][3] + bb.y;
            const int cm = col % 192;
            const int head = col / 192;
            if (cm < 64) {
                const size_t o0 = (size_t)row0 * EMB + head * 64 + cm;
                *(uint32_t*)(g_q + o0)           = packh2(v00, v01);
                *(uint32_t*)(g_q + o0 + 8 * EMB) = packh2(v10, v11);
            } else if (cm < 128) {
                const size_t o0 = (size_t)row0 * EMB + head * 64 + (cm - 64);
                uint32_t h0, l0, h1, l1;
                split2h(v00, v01, h0, l0);
                split2h(v10, v11, h1, l1);
                *(uint32_t*)(g_k_hi + o0)           = h0;
                *(uint32_t*)(g_k_lo + o0)           = l0;
                *(uint32_t*)(g_k_hi + o0 + 8 * EMB) = h1;
                *(uint32_t*)(g_k_lo + o0 + 8 * EMB) = l1;
            } else {
                const size_t o0 = (size_t)row0 * EMB + head * 64 + (cm - 128);
                *(uint32_t*)(g_v + o0)           = packh2(v00, v01);
                *(uint32_t*)(g_v + o0 + 8 * EMB) = packh2(v10, v11);
            }
        }
    }
#undef GEMM_ISSUE
}

// ---------------------------------------------------------------------------
// Kernel 2: flash attention. Grid (S/128, H, B), 256 threads, 2 CTAs/SM.
// S = qh_fp16 · (k_hi + k_lo)  (2-term asymmetric fp16; dropped ql·k term
// contributes ~1.7e-4 to P). PV single-term fp16. BQ=128, BN=64,
// 2-slot KV ring (Khi, Klo, V fp16), exp2 softmax. smem 73728.
// ---------------------------------------------------------------------------
#define ATS      72
#define QTILE_B  (128 * ATS * 2)               // 18432
#define KT64_B   (64 * ATS * 2)                // 9216
#define KVBASE   QTILE_B
#define SLOT_B   (3 * KT64_B)                  // 27648 (Khi, Klo, V)
#define OKh      0
#define OKl      KT64_B
#define OV       (2 * KT64_B)
#define ATTN_SMEM_BYTES (KVBASE + 2 * SLOT_B)  // 73728 -> 2 CTAs/SM
#define NKT      (SEQ / 64)                    // 32

__global__ void __launch_bounds__(256, 2)
attn_fp16(float* __restrict__ out)
{
    extern __shared__ char shb[];
    const uint32_t sb = (uint32_t)__cvta_generic_to_shared(shb);

    const int tid  = threadIdx.x;
    const int lane = tid & 31, wrp = tid >> 5;
    const int g = lane >> 2, tig = lane & 3;
    const int qt = blockIdx.x, h = blockIdx.y, b = blockIdx.z;

    const int a_row = (lane & 7) + 8 * ((lane >> 3) & 1);
    const int a_col = 8 * (lane >> 4);
    const int k_row = (lane & 7) + 8 * (lane >> 4);
    const int k_col = 8 * ((lane >> 3) & 1);

#define KV_ISSUE(slot, tt)                                                   \
    do {                                                                     \
        const uint32_t kbase = sb + KVBASE + (uint32_t)(slot) * SLOT_B;      \
        _Pragma("unroll")                                                    \
        for (int i = 0; i < 2; i++) {                                        \
            int ch = tid + 256 * i;                                          \
            int r = ch >> 3, sg = ch & 7;                                    \
            size_t go = (size_t)(b * SEQ + (tt) * 64 + r) * EMB + h * 64 + sg * 8; \
            uint32_t d = (uint32_t)(r * ATS + sg * 8) * 2;                   \
            CPA16(kbase + OKh + d, g_k_hi + go);                             \
            CPA16(kbase + OKl + d, g_k_lo + go);                             \
            CPA16(kbase + OV  + d, g_v + go);                                \
        }                                                                    \
        CPA_COMMIT();                                                        \
    } while (0)

    // ---- prologue: Q (group 0), KV tile 0 (group 1) ----
#pragma unroll
    for (int i = 0; i < 4; i++) {
        const int ch = tid + 256 * i;
        const int r = ch >> 3, sg = ch & 7;
        const size_t go = (size_t)(b * SEQ + qt * 128 + r) * EMB + h * 64 + sg * 8;
        CPA16(sb + (uint32_t)(r * ATS + sg * 8) * 2, g_q + go);
    }
    CPA_COMMIT();
    KV_ISSUE(0, 0);
    CPA_WAIT1();           // Q landed
    __syncthreads();

    // Q fragments (fp16, loop invariant)
    uint32_t qh[4][4];
#pragma unroll
    for (int kk = 0; kk < 4; kk++) {
        const uint32_t off =
            (uint32_t)((16 * wrp + a_row) * ATS + kk * 16 + a_col) * 2;
        LDSM_X4(qh[kk][0], qh[kk][1], qh[kk][2], qh[kk][3], sb + off);
    }

    float m0 = -1e30f, m1 = -1e30f, l0 = 0.0f, l1 = 0.0f;
    float o[8][4];
#pragma unroll
    for (int j = 0; j < 8; j++)
        o[j][0] = o[j][1] = o[j][2] = o[j][3] = 0.0f;

    const float* wscp = g_wsc + b * SEQ;
    const float* wvlp = g_wvl + b * SEQ;

    for (int t = 0; t < NKT; t++) {
        const int slot = t & 1;
        CPA_WAIT0();
        __syncthreads();

        if (t + 1 < NKT)
            KV_ISSUE(slot ^ 1, t + 1);

        const uint32_t kb = sb + KVBASE + (uint32_t)slot * SLOT_B;

        // ---- S = qh (kh + kl) : 16 q-rows x 64 keys per warp ----
        float s[8][4];
#pragma unroll
        for (int j = 0; j < 8; j++)
            s[j][0] = s[j][1] = s[j][2] = s[j][3] = 0.0f;

#pragma unroll
        for (int kk = 0; kk < 4; kk++) {
#pragma unroll
            for (int jp = 0; jp < 4; jp++) {
                const uint32_t off =
                    (uint32_t)((jp * 16 + k_row) * ATS + kk * 16 + k_col) * 2;
                uint32_t kh0, kh1, kh2, kh3, kl0, kl1, kl2, kl3;
                LDSM_X4(kh0, kh1, kh2, kh3, kb + OKh + off);
                LDSM_X4(kl0, kl1, kl2, kl3, kb + OKl + off);
                MMA_FP16(s[2 * jp],     qh[kk][0], qh[kk][1], qh[kk][2], qh[kk][3], kh0, kh1);
                MMA_FP16(s[2 * jp + 1], qh[kk][0], qh[kk][1], qh[kk][2], qh[kk][3], kh2, kh3);
                MMA_FP16(s[2 * jp],     qh[kk][0], qh[kk][1], qh[kk][2], qh[kk][3], kl0, kl1);
                MMA_FP16(s[2 * jp + 1], qh[kk][0], qh[kk][1], qh[kk][2], qh[kk][3], kl2, kl3);
            }
        }

        // ---- logit transform (log2 domain) + row max ----
        const int wbase = t * 64;
        float mx0 = -1e30f, mx1 = -1e30f;
#pragma unroll
        for (int j = 0; j < 8; j++) {
            const float2 ws = *(const float2*)&wscp[wbase + j * 8 + 2 * tig];
            const float2 wv = *(const float2*)&wvlp[wbase + j * 8 + 2 * tig];
            s[j][0] = fmaf(s[j][0], ws.x, wv.x);
            s[j][1] = fmaf(s[j][1], ws.y, wv.y);
            s[j][2] = fmaf(s[j][2], ws.x, wv.x);
            s[j][3] = fmaf(s[j][3], ws.y, wv.y);
            mx0 = fmaxf(mx0, fmaxf(s[j][0], s[j][1]));
            mx1 = fmaxf(mx1, fmaxf(s[j][2], s[j][3]));
        }
        mx0 = fmaxf(mx0, __shfl_xor_sync(0xffffffffu, mx0, 1));
        mx0 = fmaxf(mx0, __shfl_xor_sync(0xffffffffu, mx0, 2));
        mx1 = fmaxf(mx1, __shfl_xor_sync(0xffffffffu, mx1, 1));
        mx1 = fmaxf(mx1, __shfl_xor_sync(0xffffffffu, mx1, 2));

        const float mn0 = fmaxf(m0, mx0), mn1 = fmaxf(m1, mx1);
        const float c0 = exp2f(m0 - mn0), c1 = exp2f(m1 - mn1);
        m0 = mn0; m1 = mn1;

        float rs0 = 0.0f, rs1 = 0.0f;
#pragma unroll
        for (int j = 0; j < 8; j++) {
            s[j][0] = exp2f(s[j][0] - m0);
            s[j][1] = exp2f(s[j][1] - m0);
            s[j][2] = exp2f(s[j][2] - m1);
            s[j][3] = exp2f(s[j][3] - m1);
            rs0 += s[j][0] + s[j][1];
            rs1 += s[j][2] + s[j][3];
        }
        rs0 += __shfl_xor_sync(0xffffffffu, rs0, 1);
        rs0 += __shfl_xor_sync(0xffffffffu, rs0, 2);
        rs1 += __shfl_xor_sync(0xffffffffu, rs1, 1);
        rs1 += __shfl_xor_sync(0xffffffffu, rs1, 2);

        l0 = l0 * c0 + rs0;
        l1 = l1 * c1 + rs1;
#pragma unroll
        for (int j = 0; j < 8; j++) {
            o[j][0] *= c0; o[j][1] *= c0;
            o[j][2] *= c1; o[j][3] *= c1;
        }

        // ---- O += P V : single-term fp16 ----
#pragma unroll
        for (int kk = 0; kk < 4; kk++) {
            uint32_t ph[4];
            ph[0] = packh2(s[2 * kk][0],     s[2 * kk][1]);
            ph[1] = packh2(s[2 * kk][2],     s[2 * kk][3]);
            ph[2] = packh2(s[2 * kk + 1][0], s[2 * kk + 1][1]);
            ph[3] = packh2(s[2 * kk + 1][2], s[2 * kk + 1][3]);
#pragma unroll
            for (int jp = 0; jp < 4; jp++) {
                const uint32_t off =
                    (uint32_t)((kk * 16 + a_row) * ATS + jp * 16 + a_col) * 2;
                uint32_t vh0, vh1, vh2, vh3;
                LDSM_X4_T(vh0, vh1, vh2, vh3, kb + OV + off);
                MMA_FP16(o[2 * jp],     ph[0], ph[1], ph[2], ph[3], vh0, vh1);
                MMA_FP16(o[2 * jp + 1], ph[0], ph[1], ph[2], ph[3], vh2, vh3);
            }
        }
    }

    // ---- epilogue ----
    const float i0 = 1.0f / l0, i1 = 1.0f / l1;
    const int grow = b * SEQ + qt * 128 + 16 * wrp + g;
#pragma unroll
    for (int j = 0; j < 8; j++) {
        const int col = h * 64 + j * 8 + 2 * tig;
        *(float2*)(out + (size_t)grow * EMB + col) =
            make_float2(o[j][0] * i0, o[j][1] * i0);
        *(float2*)(out + (size_t)(grow + 8) * EMB + col) =
            make_float2(o[j][2] * i1, o[j][3] * i1);
    }
#undef KV_ISSUE
}

// ---------------------------------------------------------------------------
extern "C" void kernel_launch(void* const* d_in, const int* in_sizes, int n_in,
                              void* d_out, int out_size)
{
    const float* x    = (const float*)d_in[0];
    const float* w    = (const float*)d_in[1];
    const float* Wqkv = (const float*)d_in[2];
    const float* bqkv = (const float*)d_in[3];
    float* out = (float*)d_out;

    cudaFuncSetAttribute(qkv_gemm,
                         cudaFuncAttributeMaxDynamicSharedMemorySize,
                         GEMM_SMEM_BYTES);
    cudaFuncSetAttribute(attn_fp16,
                         cudaFuncAttributeMaxDynamicSharedMemorySize,
                         ATTN_SMEM_BYTES);

    split_x_kernel<<<MROWS * EMB / 4 / 256, 256>>>((const float4*)x);
    split_w_kernel<<<EMB * QKVN / 4 / 256, 256>>>((const float4*)Wqkv);
    wprep_kernel<<<(BATCH * SEQ + 255) / 256, 256>>>(w);

    dim3 g1(QKVN / 128, MROWS / 128);            // (24, 32)
    qkv_gemm<<<g1, 256, GEMM_SMEM_BYTES>>>(bqkv);

    dim3 g2(SEQ / 128, NHEAD, BATCH);            // (16, 16, 2)
    attn_fp16<<<g2, 256, ATTN_SMEM_BYTES>>>(out);
}

// round 13
// speedup vs baseline: 1.2679x; 1.1842x over previous
#include <cuda_runtime.h>
#include <cuda_bf16.h>
#include <cuda_fp16.h>
#include <math.h>
#include <stdint.h>

// Problem constants
#define BATCH   2
#define SEQ     2048
#define EMB     1024
#define NHEAD   16
#define QKVN    3072
#define MROWS   4096
#define TINY_F  1.17549435e-38f
#define SCALE_Q 0.125f
#define LOG2E   1.4426950408889634f
#define BIGNEG2 -1.3e16f
#define BIGPOS2  1.3e16f

// Global scratch (all fp16)
__device__ __half g_x_h[(size_t)MROWS * EMB];    // x fp16 (single)
__device__ __half g_w_hi[(size_t)EMB * QKVN];    // (W*32) fp16 hi
__device__ __half g_w_lo[(size_t)EMB * QKVN];    // (W*32) fp16 lo
__device__ __half g_q[(size_t)MROWS * EMB];      // Q fp16   [row][h*64+d]
__device__ __half g_k_hi[(size_t)MROWS * EMB];   // K fp16 hi
__device__ __half g_k_lo[(size_t)MROWS * EMB];   // K fp16 lo
__device__ __half g_v[(size_t)MROWS * EMB];      // V fp16
__device__ float g_wsc[BATCH * SEQ];             // log2-domain scale
__device__ float g_wvl[BATCH * SEQ];             // log2-domain bias

// ---------------------------------------------------------------------------
// PTX helpers
// ---------------------------------------------------------------------------
#define MMA_FP16(c, a0, a1, a2, a3, b0, b1)                                  \
    asm volatile(                                                            \
        "mma.sync.aligned.m16n8k16.row.col.f32.f16.f16.f32 "                 \
        "{%0,%1,%2,%3}, {%4,%5,%6,%7}, {%8,%9}, {%0,%1,%2,%3};"              \
        : "+f"((c)[0]), "+f"((c)[1]), "+f"((c)[2]), "+f"((c)[3])             \
        : "r"(a0), "r"(a1), "r"(a2), "r"(a3), "r"(b0), "r"(b1))

#define LDSM_X4(r0, r1, r2, r3, a)                                           \
    asm volatile("ldmatrix.sync.aligned.m8n8.x4.shared.b16 {%0,%1,%2,%3}, [%4];" \
        : "=r"(r0), "=r"(r1), "=r"(r2), "=r"(r3) : "r"(a))

#define LDSM_X4_T(r0, r1, r2, r3, a)                                         \
    asm volatile("ldmatrix.sync.aligned.m8n8.x4.trans.shared.b16 {%0,%1,%2,%3}, [%4];" \
        : "=r"(r0), "=r"(r1), "=r"(r2), "=r"(r3) : "r"(a))

#define CPA16(dst_u32, src_ptr)                                              \
    asm volatile("cp.async.cg.shared.global [%0], [%1], 16;"                 \
                 :: "r"(dst_u32), "l"(src_ptr))
#define CPA_COMMIT() asm volatile("cp.async.commit_group;")
#define CPA_WAIT1()  asm volatile("cp.async.wait_group 1;")
#define CPA_WAIT0()  asm volatile("cp.async.wait_group 0;")

__device__ __forceinline__ uint32_t packh2(float x, float y)
{
    __half2 h = __floats2half2_rn(x, y);
    return *reinterpret_cast<uint32_t*>(&h);
}

__device__ __forceinline__ void split2h(float x, float y,
                                        uint32_t& hi, uint32_t& lo)
{
    __half2 h = __floats2half2_rn(x, y);
    float rx = x - __half2float(h.x);
    float ry = y - __half2float(h.y);
    __half2 l = __floats2half2_rn(rx, ry);
    hi = *reinterpret_cast<uint32_t*>(&h);
    lo = *reinterpret_cast<uint32_t*>(&l);
}

// ---------------------------------------------------------------------------
// Prep kernels
// ---------------------------------------------------------------------------
__global__ void prep_x_kernel(const float4* __restrict__ in)
{
    int i = blockIdx.x * blockDim.x + threadIdx.x;
    if (i < MROWS * EMB / 4) {
        float4 v = in[i];
        uint2 p;
        p.x = packh2(v.x, v.y);
        p.y = packh2(v.z, v.w);
        ((uint2*)g_x_h)[i] = p;
    }
}

// W stored scaled by 32 (unit-scale values -> fp16 lo stays in normal range);
// the GEMM epilogue multiplies the accumulator by exact 1/32.
__global__ void prep_w_kernel(const float4* __restrict__ in)
{
    int i = blockIdx.x * blockDim.x + threadIdx.x;
    if (i < EMB * QKVN / 4) {
        float4 v = in[i];
        uint2 uh, ul;
        split2h(v.x * 32.0f, v.y * 32.0f, uh.x, ul.x);
        split2h(v.z * 32.0f, v.w * 32.0f, uh.y, ul.y);
        ((uint2*)g_w_hi)[i] = uh;
        ((uint2*)g_w_lo)[i] = ul;
    }
}

__global__ void wprep_kernel(const float* __restrict__ w)
{
    int i = blockIdx.x * blockDim.x + threadIdx.x;
    if (i < BATCH * SEQ) {
        const float v = w[i];
        const bool z = (v == 0.0f), on = (v == 1.0f);
        g_wsc[i] = (z || on) ? 0.0f : SCALE_Q * LOG2E;
        g_wvl[i] = z ? BIGNEG2 : (on ? BIGPOS2 : log2f(v + TINY_F));
    }
}

// ---------------------------------------------------------------------------
// Kernel 1: qkv = x @ W + b, asymmetric fp16x2 mma (x single, W hi/lo).
// CTA 128x128, BK=32, 256 threads. 2-buffer ring, issue-before-wait.
// Epilogue: acc/32 + bias, routed per head region to q / k(hi,lo) / v fp16.
// ---------------------------------------------------------------------------
#define GA_STR 40
#define GB_STR 136
#define GA_H   (128 * GA_STR)                  // 5120 halves (A hi only)
#define GB_H   (32 * GB_STR)                   // 4352 halves
#define GBUF_H (GA_H + 2 * GB_H)               // 13824 halves / buffer
#define GEMM_SMEM_BYTES (2 * GBUF_H * 2)       // 55296

__global__ void __launch_bounds__(256)
qkv_gemm(const float* __restrict__ bias)
{
    extern __shared__ __half sh[];
    const uint32_t sbase = (uint32_t)__cvta_generic_to_shared(sh);

    const int tid  = threadIdx.x;
    const int lane = tid & 31, wid = tid >> 5;
    const int g = lane >> 2, tig = lane & 3;
    const int wr = wid >> 1, wc = wid & 1;
    const int bn = blockIdx.x * 128, bm = blockIdx.y * 128;

    const uint32_t OA  = 0;
    const uint32_t OBh = GA_H * 2, OBl = (GA_H + GB_H) * 2;
    const uint32_t BUFB = GBUF_H * 2;

    float acc[2][8][4];
#pragma unroll
    for (int mt = 0; mt < 2; mt++)
#pragma unroll
        for (int j = 0; j < 8; j++)
#pragma unroll
            for (int q = 0; q < 4; q++) acc[mt][j][q] = 0.0f;

    const int a_row = (lane & 7) + 8 * ((lane >> 3) & 1);
    const int a_col = 8 * (lane >> 4);
    const int b_row = lane & 15;
    const int b_col = 8 * (lane >> 4);

    // A tile: 128x32 fp16 = 512 16B-chunks -> 2/thread.
    // B tiles: 32x128 x2 arrays = 1024 chunks -> 4/thread.
#define GEMM_ISSUE(buf, kt)                                                  \
    do {                                                                     \
        const uint32_t sb = sbase + (buf) * BUFB;                            \
        _Pragma("unroll")                                                    \
        for (int i = 0; i < 2; i++) {                                        \
            int ch = tid + 256 * i;                                          \
            int r = ch >> 2, sg = ch & 3;                                    \
            size_t go = (size_t)(bm + r) * EMB + (kt) * 32 + sg * 8;         \
            CPA16(sb + OA + (uint32_t)(r * GA_STR + sg * 8) * 2, g_x_h + go);\
        }                                                                    \
        _Pragma("unroll")                                                    \
        for (int i = 0; i < 2; i++) {                                        \
            int ch = tid + 256 * i;                                          \
            int r = ch >> 4, sg = ch & 15;                                   \
            size_t go = (size_t)((kt) * 32 + r) * QKVN + bn + sg * 8;        \
            uint32_t d = sb + (uint32_t)(r * GB_STR + sg * 8) * 2;           \
            CPA16(d + OBh, g_w_hi + go);                                     \
            CPA16(d + OBl, g_w_lo + go);                                     \
        }                                                                    \
    } while (0)

    GEMM_ISSUE(0, 0);
    CPA_COMMIT();

    for (int kt = 0; kt < 32; kt++) {
        const int buf = kt & 1;
        if (kt < 31) {
            GEMM_ISSUE(buf ^ 1, kt + 1);
            CPA_COMMIT();
            CPA_WAIT1();
        } else {
            CPA_WAIT0();
        }
        __syncthreads();

        const uint32_t sb = sbase + buf * BUFB;
#pragma unroll
        for (int ks = 0; ks < 2; ks++) {
            const int k0 = ks * 16;
            uint32_t ah[2][4];
#pragma unroll
            for (int mt = 0; mt < 2; mt++) {
                const uint32_t off =
                    (uint32_t)((wr * 32 + mt * 16 + a_row) * GA_STR + k0 + a_col) * 2;
                LDSM_X4(ah[mt][0], ah[mt][1], ah[mt][2], ah[mt][3], sb + OA + off);
            }
#pragma unroll
            for (int jp = 0; jp < 4; jp++) {
                const uint32_t off =
                    (uint32_t)((k0 + b_row) * GB_STR + wc * 64 + jp * 16 + b_col) * 2;
                uint32_t bh0, bh1, bh2, bh3, bl0, bl1, bl2, bl3;
                LDSM_X4_T(bh0, bh1, bh2, bh3, sb + OBh + off);
                LDSM_X4_T(bl0, bl1, bl2, bl3, sb + OBl + off);
                // term hi (4 independent accs), then term lo
                MMA_FP16(acc[0][2 * jp],     ah[0][0], ah[0][1], ah[0][2], ah[0][3], bh0, bh1);
                MMA_FP16(acc[1][2 * jp],     ah[1][0], ah[1][1], ah[1][2], ah[1][3], bh0, bh1);
                MMA_FP16(acc[0][2 * jp + 1], ah[0][0], ah[0][1], ah[0][2], ah[0][3], bh2, bh3);
                MMA_FP16(acc[1][2 * jp + 1], ah[1][0], ah[1][1], ah[1][2], ah[1][3], bh2, bh3);
                MMA_FP16(acc[0][2 * jp],     ah[0][0], ah[0][1], ah[0][2], ah[0][3], bl0, bl1);
                MMA_FP16(acc[1][2 * jp],     ah[1][0], ah[1][1], ah[1][2], ah[1][3], bl0, bl1);
                MMA_FP16(acc[0][2 * jp + 1], ah[0][0], ah[0][1], ah[0][2], ah[0][3], bl2, bl3);
                MMA_FP16(acc[1][2 * jp + 1], ah[1][0], ah[1][1], ah[1][2], ah[1][3], bl2, bl3);
            }
        }
        __syncthreads();
    }

    // Epilogue: rescale (W stored x32), add bias, route per head region.
#pragma unroll
    for (int mt = 0; mt < 2; mt++) {
        const int row0 = bm + wr * 32 + mt * 16 + g;
#pragma unroll
        for (int j = 0; j < 8; j++) {
            const int col = bn + wc * 64 + j * 8 + 2 * tig;
            const float2 bb = *(const float2*)(bias + col);
            const float v00 = acc[mt][j][0] * 0.03125f + bb.x;
            const float v01 = acc[mt][j][1] * 0.03125f + bb.y;
            const float v10 = acc[mt][j][2] * 0.03125f + bb.x;
            const float v11 = acc[mt][j][3] * 0.03125f + bb.y;
            const int cm = col % 192;
            const int head = col / 192;
            if (cm < 64) {
                const size_t o0 = (size_t)row0 * EMB + head * 64 + cm;
                *(uint32_t*)(g_q + o0)           = packh2(v00, v01);
                *(uint32_t*)(g_q + o0 + 8 * EMB) = packh2(v10, v11);
            } else if (cm < 128) {
                const size_t o0 = (size_t)row0 * EMB + head * 64 + (cm - 64);
                uint32_t h0, l0, h1, l1;
                split2h(v00, v01, h0, l0);
                split2h(v10, v11, h1, l1);
                *(uint32_t*)(g_k_hi + o0)           = h0;
                *(uint32_t*)(g_k_lo + o0)           = l0;
                *(uint32_t*)(g_k_hi + o0 + 8 * EMB) = h1;
                *(uint32_t*)(g_k_lo + o0 + 8 * EMB) = l1;
            } else {
                const size_t o0 = (size_t)row0 * EMB + head * 64 + (cm - 128);
                *(uint32_t*)(g_v + o0)           = packh2(v00, v01);
                *(uint32_t*)(g_v + o0 + 8 * EMB) = packh2(v10, v11);
            }
        }
    }
#undef GEMM_ISSUE
}

// ---------------------------------------------------------------------------
// Kernel 2: flash attention (unchanged from R12). Grid (S/128, H, B),
// 256 threads, 2 CTAs/SM. S = q_fp16 · (k_hi + k_lo); PV single-term fp16.
// BQ=128, BN=64, 2-slot KV ring, exp2 softmax. smem 73728.
// ---------------------------------------------------------------------------
#define ATS      72
#define QTILE_B  (128 * ATS * 2)               // 18432
#define KT64_B   (64 * ATS * 2)                // 9216
#define KVBASE   QTILE_B
#define SLOT_B   (3 * KT64_B)                  // 27648 (Khi, Klo, V)
#define OKh      0
#define OKl      KT64_B
#define OV       (2 * KT64_B)
#define ATTN_SMEM_BYTES (KVBASE + 2 * SLOT_B)  // 73728 -> 2 CTAs/SM
#define NKT      (SEQ / 64)                    // 32

__global__ void __launch_bounds__(256, 2)
attn_fp16(float* __restrict__ out)
{
    extern __shared__ char shb[];
    const uint32_t sb = (uint32_t)__cvta_generic_to_shared(shb);

    const int tid  = threadIdx.x;
    const int lane = tid & 31, wrp = tid >> 5;
    const int g = lane >> 2, tig = lane & 3;
    const int qt = blockIdx.x, h = blockIdx.y, b = blockIdx.z;

    const int a_row = (lane & 7) + 8 * ((lane >> 3) & 1);
    const int a_col = 8 * (lane >> 4);
    const int k_row = (lane & 7) + 8 * (lane >> 4);
    const int k_col = 8 * ((lane >> 3) & 1);

#define KV_ISSUE(slot, tt)                                                   \
    do {                                                                     \
        const uint32_t kbase = sb + KVBASE + (uint32_t)(slot) * SLOT_B;      \
        _Pragma("unroll")                                                    \
        for (int i = 0; i < 2; i++) {                                        \
            int ch = tid + 256 * i;                                          \
            int r = ch >> 3, sg = ch & 7;                                    \
            size_t go = (size_t)(b * SEQ + (tt) * 64 + r) * EMB + h * 64 + sg * 8; \
            uint32_t d = (uint32_t)(r * ATS + sg * 8) * 2;                   \
            CPA16(kbase + OKh + d, g_k_hi + go);                             \
            CPA16(kbase + OKl + d, g_k_lo + go);                             \
            CPA16(kbase + OV  + d, g_v + go);                                \
        }                                                                    \
        CPA_COMMIT();                                                        \
    } while (0)

    // ---- prologue: Q (group 0), KV tile 0 (group 1) ----
#pragma unroll
    for (int i = 0; i < 4; i++) {
        const int ch = tid + 256 * i;
        const int r = ch >> 3, sg = ch & 7;
        const size_t go = (size_t)(b * SEQ + qt * 128 + r) * EMB + h * 64 + sg * 8;
        CPA16(sb + (uint32_t)(r * ATS + sg * 8) * 2, g_q + go);
    }
    CPA_COMMIT();
    KV_ISSUE(0, 0);
    CPA_WAIT1();           // Q landed
    __syncthreads();

    // Q fragments (fp16, loop invariant)
    uint32_t qh[4][4];
#pragma unroll
    for (int kk = 0; kk < 4; kk++) {
        const uint32_t off =
            (uint32_t)((16 * wrp + a_row) * ATS + kk * 16 + a_col) * 2;
        LDSM_X4(qh[kk][0], qh[kk][1], qh[kk][2], qh[kk][3], sb + off);
    }

    float m0 = -1e30f, m1 = -1e30f, l0 = 0.0f, l1 = 0.0f;
    float o[8][4];
#pragma unroll
    for (int j = 0; j < 8; j++)
        o[j][0] = o[j][1] = o[j][2] = o[j][3] = 0.0f;

    const float* wscp = g_wsc + b * SEQ;
    const float* wvlp = g_wvl + b * SEQ;

    for (int t = 0; t < NKT; t++) {
        const int slot = t & 1;
        CPA_WAIT0();
        __syncthreads();

        if (t + 1 < NKT)
            KV_ISSUE(slot ^ 1, t + 1);

        const uint32_t kb = sb + KVBASE + (uint32_t)slot * SLOT_B;

        // ---- S = qh (kh + kl) : 16 q-rows x 64 keys per warp ----
        float s[8][4];
#pragma unroll
        for (int j = 0; j < 8; j++)
            s[j][0] = s[j][1] = s[j][2] = s[j][3] = 0.0f;

#pragma unroll
        for (int kk = 0; kk < 4; kk++) {
#pragma unroll
            for (int jp = 0; jp < 4; jp++) {
                const uint32_t off =
                    (uint32_t)((jp * 16 + k_row) * ATS + kk * 16 + k_col) * 2;
                uint32_t kh0, kh1, kh2, kh3, kl0, kl1, kl2, kl3;
                LDSM_X4(kh0, kh1, kh2, kh3, kb + OKh + off);
                LDSM_X4(kl0, kl1, kl2, kl3, kb + OKl + off);
                MMA_FP16(s[2 * jp],     qh[kk][0], qh[kk][1], qh[kk][2], qh[kk][3], kh0, kh1);
                MMA_FP16(s[2 * jp + 1], qh[kk][0], qh[kk][1], qh[kk][2], qh[kk][3], kh2, kh3);
                MMA_FP16(s[2 * jp],     qh[kk][0], qh[kk][1], qh[kk][2], qh[kk][3], kl0, kl1);
                MMA_FP16(s[2 * jp + 1], qh[kk][0], qh[kk][1], qh[kk][2], qh[kk][3], kl2, kl3);
            }
        }

        // ---- logit transform (log2 domain) + row max ----
        const int wbase = t * 64;
        float mx0 = -1e30f, mx1 = -1e30f;
#pragma unroll
        for (int j = 0; j < 8; j++) {
            const float2 ws = *(const float2*)&wscp[wbase + j * 8 + 2 * tig];
            const float2 wv = *(const float2*)&wvlp[wbase + j * 8 + 2 * tig];
            s[j][0] = fmaf(s[j][0], ws.x, wv.x);
            s[j][1] = fmaf(s[j][1], ws.y, wv.y);
            s[j][2] = fmaf(s[j][2], ws.x, wv.x);
            s[j][3] = fmaf(s[j][3], ws.y, wv.y);
            mx0 = fmaxf(mx0, fmaxf(s[j][0], s[j][1]));
            mx1 = fmaxf(mx1, fmaxf(s[j][2], s[j][3]));
        }
        mx0 = fmaxf(mx0, __shfl_xor_sync(0xffffffffu, mx0, 1));
        mx0 = fmaxf(mx0, __shfl_xor_sync(0xffffffffu, mx0, 2));
        mx1 = fmaxf(mx1, __shfl_xor_sync(0xffffffffu, mx1, 1));
        mx1 = fmaxf(mx1, __shfl_xor_sync(0xffffffffu, mx1, 2));

        const float mn0 = fmaxf(m0, mx0), mn1 = fmaxf(m1, mx1);
        const float c0 = exp2f(m0 - mn0), c1 = exp2f(m1 - mn1);
        m0 = mn0; m1 = mn1;

        float rs0 = 0.0f, rs1 = 0.0f;
#pragma unroll
        for (int j = 0; j < 8; j++) {
            s[j][0] = exp2f(s[j][0] - m0);
            s[j][1] = exp2f(s[j][1] - m0);
            s[j][2] = exp2f(s[j][2] - m1);
            s[j][3] = exp2f(s[j][3] - m1);
            rs0 += s[j][0] + s[j][1];
            rs1 += s[j][2] + s[j][3];
        }
        rs0 += __shfl_xor_sync(0xffffffffu, rs0, 1);
        rs0 += __shfl_xor_sync(0xffffffffu, rs0, 2);
        rs1 += __shfl_xor_sync(0xffffffffu, rs1, 1);
        rs1 += __shfl_xor_sync(0xffffffffu, rs1, 2);

        l0 = l0 * c0 + rs0;
        l1 = l1 * c1 + rs1;
#pragma unroll
        for (int j = 0; j < 8; j++) {
            o[j][0] *= c0; o[j][1] *= c0;
            o[j][2] *= c1; o[j][3] *= c1;
        }

        // ---- O += P V : single-term fp16 ----
#pragma unroll
        for (int kk = 0; kk < 4; kk++) {
            uint32_t ph[4];
            ph[0] = packh2(s[2 * kk][0],     s[2 * kk][1]);
            ph[1] = packh2(s[2 * kk][2],     s[2 * kk][3]);
            ph[2] = packh2(s[2 * kk + 1][0], s[2 * kk + 1][1]);
            ph[3] = packh2(s[2 * kk + 1][2], s[2 * kk + 1][3]);
#pragma unroll
            for (int jp = 0; jp < 4; jp++) {
                const uint32_t off =
                    (uint32_t)((kk * 16 + a_row) * ATS + jp * 16 + a_col) * 2;
                uint32_t vh0, vh1, vh2, vh3;
                LDSM_X4_T(vh0, vh1, vh2, vh3, kb + OV + off);
                MMA_FP16(o[2 * jp],     ph[0], ph[1], ph[2], ph[3], vh0, vh1);
                MMA_FP16(o[2 * jp + 1], ph[0], ph[1], ph[2], ph[3], vh2, vh3);
            }
        }
    }

    // ---- epilogue ----
    const float i0 = 1.0f / l0, i1 = 1.0f / l1;
    const int grow = b * SEQ + qt * 128 + 16 * wrp + g;
#pragma unroll
    for (int j = 0; j < 8; j++) {
        const int col = h * 64 + j * 8 + 2 * tig;
        *(float2*)(out + (size_t)grow * EMB + col) =
            make_float2(o[j][0] * i0, o[j][1] * i0);
        *(float2*)(out + (size_t)(grow + 8) * EMB + col) =
            make_float2(o[j][2] * i1, o[j][3] * i1);
    }
#undef KV_ISSUE
}

// ---------------------------------------------------------------------------
extern "C" void kernel_launch(void* const* d_in, const int* in_sizes, int n_in,
                              void* d_out, int out_size)
{
    const float* x    = (const float*)d_in[0];
    const float* w    = (const float*)d_in[1];
    const float* Wqkv = (const float*)d_in[2];
    const float* bqkv = (const float*)d_in[3];
    float* out = (float*)d_out;

    cudaFuncSetAttribute(qkv_gemm,
                         cudaFuncAttributeMaxDynamicSharedMemorySize,
                         GEMM_SMEM_BYTES);
    cudaFuncSetAttribute(attn_fp16,
                         cudaFuncAttributeMaxDynamicSharedMemorySize,
                         ATTN_SMEM_BYTES);

    prep_x_kernel<<<MROWS * EMB / 4 / 256, 256>>>((const float4*)x);
    prep_w_kernel<<<EMB * QKVN / 4 / 256, 256>>>((const float4*)Wqkv);
    wprep_kernel<<<(BATCH * SEQ + 255) / 256, 256>>>(w);

    dim3 g1(QKVN / 128, MROWS / 128);            // (24, 32)
    qkv_gemm<<<g1, 256, GEMM_SMEM_BYTES>>>(bqkv);

    dim3 g2(SEQ / 128, NHEAD, BATCH);            // (16, 16, 2)
    attn_fp16<<<g2, 256, ATTN_SMEM_BYTES>>>(out);
}

// round 14
// speedup vs baseline: 1.2978x; 1.0236x over previous
#include <cuda_runtime.h>
#include <cuda_bf16.h>
#include <cuda_fp16.h>
#include <math.h>
#include <stdint.h>

// Problem constants
#define BATCH   2
#define SEQ     2048
#define EMB     1024
#define NHEAD   16
#define QKVN    3072
#define MROWS   4096
#define TINY_F  1.17549435e-38f
#define SCALE_Q 0.125f
#define LOG2E   1.4426950408889634f
#define BIGNEG2 -1.3e16f
#define BIGPOS2  1.3e16f

// Global scratch (all fp16)
__device__ __half g_x_h[(size_t)MROWS * EMB];    // x fp16 (single)
__device__ __half g_w_hi[(size_t)EMB * QKVN];    // (W*32) fp16 hi
__device__ __half g_w_lo[(size_t)EMB * QKVN];    // (W*32) fp16 lo
__device__ __half g_q[(size_t)MROWS * EMB];      // Q fp16   [row][h*64+d]
__device__ __half g_k[(size_t)MROWS * EMB];      // K fp16 (single)
__device__ __half g_v[(size_t)MROWS * EMB];      // V fp16
__device__ float g_wsc[BATCH * SEQ];             // log2-domain scale
__device__ float g_wvl[BATCH * SEQ];             // log2-domain bias

// ---------------------------------------------------------------------------
// PTX helpers
// ---------------------------------------------------------------------------
#define MMA_FP16(c, a0, a1, a2, a3, b0, b1)                                  \
    asm volatile(                                                            \
        "mma.sync.aligned.m16n8k16.row.col.f32.f16.f16.f32 "                 \
        "{%0,%1,%2,%3}, {%4,%5,%6,%7}, {%8,%9}, {%0,%1,%2,%3};"              \
        : "+f"((c)[0]), "+f"((c)[1]), "+f"((c)[2]), "+f"((c)[3])             \
        : "r"(a0), "r"(a1), "r"(a2), "r"(a3), "r"(b0), "r"(b1))

#define LDSM_X4(r0, r1, r2, r3, a)                                           \
    asm volatile("ldmatrix.sync.aligned.m8n8.x4.shared.b16 {%0,%1,%2,%3}, [%4];" \
        : "=r"(r0), "=r"(r1), "=r"(r2), "=r"(r3) : "r"(a))

#define LDSM_X4_T(r0, r1, r2, r3, a)                                         \
    asm volatile("ldmatrix.sync.aligned.m8n8.x4.trans.shared.b16 {%0,%1,%2,%3}, [%4];" \
        : "=r"(r0), "=r"(r1), "=r"(r2), "=r"(r3) : "r"(a))

#define CPA16(dst_u32, src_ptr)                                              \
    asm volatile("cp.async.cg.shared.global [%0], [%1], 16;"                 \
                 :: "r"(dst_u32), "l"(src_ptr))
#define CPA_COMMIT() asm volatile("cp.async.commit_group;")
#define CPA_WAIT1()  asm volatile("cp.async.wait_group 1;")
#define CPA_WAIT0()  asm volatile("cp.async.wait_group 0;")

__device__ __forceinline__ uint32_t packh2(float x, float y)
{
    __half2 h = __floats2half2_rn(x, y);
    return *reinterpret_cast<uint32_t*>(&h);
}

__device__ __forceinline__ void split2h(float x, float y,
                                        uint32_t& hi, uint32_t& lo)
{
    __half2 h = __floats2half2_rn(x, y);
    float rx = x - __half2float(h.x);
    float ry = y - __half2float(h.y);
    __half2 l = __floats2half2_rn(rx, ry);
    hi = *reinterpret_cast<uint32_t*>(&h);
    lo = *reinterpret_cast<uint32_t*>(&l);
}

// ---------------------------------------------------------------------------
// Prep kernels
// ---------------------------------------------------------------------------
__global__ void prep_x_kernel(const float4* __restrict__ in)
{
    int i = blockIdx.x * blockDim.x + threadIdx.x;
    if (i < MROWS * EMB / 4) {
        float4 v = in[i];
        uint2 p;
        p.x = packh2(v.x, v.y);
        p.y = packh2(v.z, v.w);
        ((uint2*)g_x_h)[i] = p;
    }
}

// W stored scaled by 32 (unit-scale -> fp16 lo stays normal);
// GEMM epilogue multiplies the accumulator by exact 1/32.
__global__ void prep_w_kernel(const float4* __restrict__ in)
{
    int i = blockIdx.x * blockDim.x + threadIdx.x;
    if (i < EMB * QKVN / 4) {
        float4 v = in[i];
        uint2 uh, ul;
        split2h(v.x * 32.0f, v.y * 32.0f, uh.x, ul.x);
        split2h(v.z * 32.0f, v.w * 32.0f, uh.y, ul.y);
        ((uint2*)g_w_hi)[i] = uh;
        ((uint2*)g_w_lo)[i] = ul;
    }
}

__global__ void wprep_kernel(const float* __restrict__ w)
{
    int i = blockIdx.x * blockDim.x + threadIdx.x;
    if (i < BATCH * SEQ) {
        const float v = w[i];
        const bool z = (v == 0.0f), on = (v == 1.0f);
        g_wsc[i] = (z || on) ? 0.0f : SCALE_Q * LOG2E;
        g_wvl[i] = z ? BIGNEG2 : (on ? BIGPOS2 : log2f(v + TINY_F));
    }
}

// ---------------------------------------------------------------------------
// Kernel 1: qkv = x @ W + b, asymmetric fp16x2 mma (x single, W hi/lo).
// CTA 128x128, BK=32, 256 threads. 2-buffer ring, issue-before-wait.
// Epilogue: acc/32 + bias, routed per head region to q / k / v fp16.
// ---------------------------------------------------------------------------
#define GA_STR 40
#define GB_STR 136
#define GA_H   (128 * GA_STR)                  // 5120 halves
#define GB_H   (32 * GB_STR)                   // 4352 halves
#define GBUF_H (GA_H + 2 * GB_H)               // 13824 halves / buffer
#define GEMM_SMEM_BYTES (2 * GBUF_H * 2)       // 55296

__global__ void __launch_bounds__(256)
qkv_gemm(const float* __restrict__ bias)
{
    extern __shared__ __half sh[];
    const uint32_t sbase = (uint32_t)__cvta_generic_to_shared(sh);

    const int tid  = threadIdx.x;
    const int lane = tid & 31, wid = tid >> 5;
    const int g = lane >> 2, tig = lane & 3;
    const int wr = wid >> 1, wc = wid & 1;
    const int bn = blockIdx.x * 128, bm = blockIdx.y * 128;

    const uint32_t OA  = 0;
    const uint32_t OBh = GA_H * 2, OBl = (GA_H + GB_H) * 2;
    const uint32_t BUFB = GBUF_H * 2;

    float acc[2][8][4];
#pragma unroll
    for (int mt = 0; mt < 2; mt++)
#pragma unroll
        for (int j = 0; j < 8; j++)
#pragma unroll
            for (int q = 0; q < 4; q++) acc[mt][j][q] = 0.0f;

    const int a_row = (lane & 7) + 8 * ((lane >> 3) & 1);
    const int a_col = 8 * (lane >> 4);
    const int b_row = lane & 15;
    const int b_col = 8 * (lane >> 4);

#define GEMM_ISSUE(buf, kt)                                                  \
    do {                                                                     \
        const uint32_t sb = sbase + (buf) * BUFB;                            \
        _Pragma("unroll")                                                    \
        for (int i = 0; i < 2; i++) {                                        \
            int ch = tid + 256 * i;                                          \
            int r = ch >> 2, sg = ch & 3;                                    \
            size_t go = (size_t)(bm + r) * EMB + (kt) * 32 + sg * 8;         \
            CPA16(sb + OA + (uint32_t)(r * GA_STR + sg * 8) * 2, g_x_h + go);\
        }                                                                    \
        _Pragma("unroll")                                                    \
        for (int i = 0; i < 2; i++) {                                        \
            int ch = tid + 256 * i;                                          \
            int r = ch >> 4, sg = ch & 15;                                   \
            size_t go = (size_t)((kt) * 32 + r) * QKVN + bn + sg * 8;        \
            uint32_t d = sb + (uint32_t)(r * GB_STR + sg * 8) * 2;           \
            CPA16(d + OBh, g_w_hi + go);                                     \
            CPA16(d + OBl, g_w_lo + go);                                     \
        }                                                                    \
    } while (0)

    GEMM_ISSUE(0, 0);
    CPA_COMMIT();

    for (int kt = 0; kt < 32; kt++) {
        const int buf = kt & 1;
        if (kt < 31) {
            GEMM_ISSUE(buf ^ 1, kt + 1);
            CPA_COMMIT();
            CPA_WAIT1();
        } else {
            CPA_WAIT0();
        }
        __syncthreads();

        const uint32_t sb = sbase + buf * BUFB;
#pragma unroll
        for (int ks = 0; ks < 2; ks++) {
            const int k0 = ks * 16;
            uint32_t ah[2][4];
#pragma unroll
            for (int mt = 0; mt < 2; mt++) {
                const uint32_t off =
                    (uint32_t)((wr * 32 + mt * 16 + a_row) * GA_STR + k0 + a_col) * 2;
                LDSM_X4(ah[mt][0], ah[mt][1], ah[mt][2], ah[mt][3], sb + OA + off);
            }
#pragma unroll
            for (int jp = 0; jp < 4; jp++) {
                const uint32_t off =
                    (uint32_t)((k0 + b_row) * GB_STR + wc * 64 + jp * 16 + b_col) * 2;
                uint32_t bh0, bh1, bh2, bh3, bl0, bl1, bl2, bl3;
                LDSM_X4_T(bh0, bh1, bh2, bh3, sb + OBh + off);
                LDSM_X4_T(bl0, bl1, bl2, bl3, sb + OBl + off);
                MMA_FP16(acc[0][2 * jp],     ah[0][0], ah[0][1], ah[0][2], ah[0][3], bh0, bh1);
                MMA_FP16(acc[1][2 * jp],     ah[1][0], ah[1][1], ah[1][2], ah[1][3], bh0, bh1);
                MMA_FP16(acc[0][2 * jp + 1], ah[0][0], ah[0][1], ah[0][2], ah[0][3], bh2, bh3);
                MMA_FP16(acc[1][2 * jp + 1], ah[1][0], ah[1][1], ah[1][2], ah[1][3], bh2, bh3);
                MMA_FP16(acc[0][2 * jp],     ah[0][0], ah[0][1], ah[0][2], ah[0][3], bl0, bl1);
                MMA_FP16(acc[1][2 * jp],     ah[1][0], ah[1][1], ah[1][2], ah[1][3], bl0, bl1);
                MMA_FP16(acc[0][2 * jp + 1], ah[0][0], ah[0][1], ah[0][2], ah[0][3], bl2, bl3);
                MMA_FP16(acc[1][2 * jp + 1], ah[1][0], ah[1][1], ah[1][2], ah[1][3], bl2, bl3);
            }
        }
        __syncthreads();
    }

    // Epilogue: rescale (W stored x32), add bias, route per head region.
#pragma unroll
    for (int mt = 0; mt < 2; mt++) {
        const int row0 = bm + wr * 32 + mt * 16 + g;
#pragma unroll
        for (int j = 0; j < 8; j++) {
            const int col = bn + wc * 64 + j * 8 + 2 * tig;
            const float2 bb = *(const float2*)(bias + col);
            const float v00 = acc[mt][j][0] * 0.03125f + bb.x;
            const float v01 = acc[mt][j][1] * 0.03125f + bb.y;
            const float v10 = acc[mt][j][2] * 0.03125f + bb.x;
            const float v11 = acc[mt][j][3] * 0.03125f + bb.y;
            const int cm = col % 192;
            const int head = col / 192;
            __half* dst = (cm < 64) ? g_q : (cm < 128) ? g_k : g_v;
            const int d0 = (cm < 64) ? cm : (cm < 128) ? cm - 64 : cm - 128;
            const size_t o0 = (size_t)row0 * EMB + head * 64 + d0;
            *(uint32_t*)(dst + o0)           = packh2(v00, v01);
            *(uint32_t*)(dst + o0 + 8 * EMB) = packh2(v10, v11);
        }
    }
#undef GEMM_ISSUE
}

// ---------------------------------------------------------------------------
// Kernel 2: flash attention. Grid (S/128, H, B), 256 threads, 2 CTAs/SM.
// S = q·k single fp16 both sides; PV single-term fp16. BQ=128, BN=64,
// 2-slot KV ring (K, V fp16), exp2 softmax. smem 55296.
// ---------------------------------------------------------------------------
#define ATS      72
#define QTILE_B  (128 * ATS * 2)               // 18432
#define KT64_B   (64 * ATS * 2)                // 9216
#define KVBASE   QTILE_B
#define SLOT_B   (2 * KT64_B)                  // 18432 (K, V)
#define OK       0
#define OV       KT64_B
#define ATTN_SMEM_BYTES (KVBASE + 2 * SLOT_B)  // 55296 -> 2 CTAs/SM
#define NKT      (SEQ / 64)                    // 32

__global__ void __launch_bounds__(256, 2)
attn_fp16(float* __restrict__ out)
{
    extern __shared__ char shb[];
    const uint32_t sb = (uint32_t)__cvta_generic_to_shared(shb);

    const int tid  = threadIdx.x;
    const int lane = tid & 31, wrp = tid >> 5;
    const int g = lane >> 2, tig = lane & 3;
    const int qt = blockIdx.x, h = blockIdx.y, b = blockIdx.z;

    const int a_row = (lane & 7) + 8 * ((lane >> 3) & 1);
    const int a_col = 8 * (lane >> 4);
    const int k_row = (lane & 7) + 8 * (lane >> 4);
    const int k_col = 8 * ((lane >> 3) & 1);

#define KV_ISSUE(slot, tt)                                                   \
    do {                                                                     \
        const uint32_t kbase = sb + KVBASE + (uint32_t)(slot) * SLOT_B;      \
        _Pragma("unroll")                                                    \
        for (int i = 0; i < 2; i++) {                                        \
            int ch = tid + 256 * i;                                          \
            int r = ch >> 3, sg = ch & 7;                                    \
            size_t go = (size_t)(b * SEQ + (tt) * 64 + r) * EMB + h * 64 + sg * 8; \
            uint32_t d = (uint32_t)(r * ATS + sg * 8) * 2;                   \
            CPA16(kbase + OK + d, g_k + go);                                 \
            CPA16(kbase + OV + d, g_v + go);                                 \
        }                                                                    \
        CPA_COMMIT();                                                        \
    } while (0)

    // ---- prologue: Q (group 0), KV tile 0 (group 1) ----
#pragma unroll
    for (int i = 0; i < 4; i++) {
        const int ch = tid + 256 * i;
        const int r = ch >> 3, sg = ch & 7;
        const size_t go = (size_t)(b * SEQ + qt * 128 + r) * EMB + h * 64 + sg * 8;
        CPA16(sb + (uint32_t)(r * ATS + sg * 8) * 2, g_q + go);
    }
    CPA_COMMIT();
    KV_ISSUE(0, 0);
    CPA_WAIT1();           // Q landed
    __syncthreads();

    // Q fragments (fp16, loop invariant)
    uint32_t qh[4][4];
#pragma unroll
    for (int kk = 0; kk < 4; kk++) {
        const uint32_t off =
            (uint32_t)((16 * wrp + a_row) * ATS + kk * 16 + a_col) * 2;
        LDSM_X4(qh[kk][0], qh[kk][1], qh[kk][2], qh[kk][3], sb + off);
    }

    float m0 = -1e30f, m1 = -1e30f, l0 = 0.0f, l1 = 0.0f;
    float o[8][4];
#pragma unroll
    for (int j = 0; j < 8; j++)
        o[j][0] = o[j][1] = o[j][2] = o[j][3] = 0.0f;

    const float* wscp = g_wsc + b * SEQ;
    const float* wvlp = g_wvl + b * SEQ;

    for (int t = 0; t < NKT; t++) {
        const int slot = t & 1;
        CPA_WAIT0();
        __syncthreads();

        if (t + 1 < NKT)
            KV_ISSUE(slot ^ 1, t + 1);

        const uint32_t kb = sb + KVBASE + (uint32_t)slot * SLOT_B;

        // ---- S = q k^T : single fp16, 16 q-rows x 64 keys per warp ----
        float s[8][4];
#pragma unroll
        for (int j = 0; j < 8; j++)
            s[j][0] = s[j][1] = s[j][2] = s[j][3] = 0.0f;

#pragma unroll
        for (int kk = 0; kk < 4; kk++) {
#pragma unroll
            for (int jp = 0; jp < 4; jp++) {
                const uint32_t off =
                    (uint32_t)((jp * 16 + k_row) * ATS + kk * 16 + k_col) * 2;
                uint32_t kh0, kh1, kh2, kh3;
                LDSM_X4(kh0, kh1, kh2, kh3, kb + OK + off);
                MMA_FP16(s[2 * jp],     qh[kk][0], qh[kk][1], qh[kk][2], qh[kk][3], kh0, kh1);
                MMA_FP16(s[2 * jp + 1], qh[kk][0], qh[kk][1], qh[kk][2], qh[kk][3], kh2, kh3);
            }
        }

        // ---- logit transform (log2 domain) + row max ----
        const int wbase = t * 64;
        float mx0 = -1e30f, mx1 = -1e30f;
#pragma unroll
        for (int j = 0; j < 8; j++) {
            const float2 ws = *(const float2*)&wscp[wbase + j * 8 + 2 * tig];
            const float2 wv = *(const float2*)&wvlp[wbase + j * 8 + 2 * tig];
            s[j][0] = fmaf(s[j][0], ws.x, wv.x);
            s[j][1] = fmaf(s[j][1], ws.y, wv.y);
            s[j][2] = fmaf(s[j][2], ws.x, wv.x);
            s[j][3] = fmaf(s[j][3], ws.y, wv.y);
            mx0 = fmaxf(mx0, fmaxf(s[j][0], s[j][1]));
            mx1 = fmaxf(mx1, fmaxf(s[j][2], s[j][3]));
        }
        mx0 = fmaxf(mx0, __shfl_xor_sync(0xffffffffu, mx0, 1));
        mx0 = fmaxf(mx0, __shfl_xor_sync(0xffffffffu, mx0, 2));
        mx1 = fmaxf(mx1, __shfl_xor_sync(0xffffffffu, mx1, 1));
        mx1 = fmaxf(mx1, __shfl_xor_sync(0xffffffffu, mx1, 2));

        const float mn0 = fmaxf(m0, mx0), mn1 = fmaxf(m1, mx1);
        const float c0 = exp2f(m0 - mn0), c1 = exp2f(m1 - mn1);
        m0 = mn0; m1 = mn1;

        float rs0 = 0.0f, rs1 = 0.0f;
#pragma unroll
        for (int j = 0; j < 8; j++) {
            s[j][0] = exp2f(s[j][0] - m0);
            s[j][1] = exp2f(s[j][1] - m0);
            s[j][2] = exp2f(s[j][2] - m1);
            s[j][3] = exp2f(s[j][3] - m1);
            rs0 += s[j][0] + s[j][1];
            rs1 += s[j][2] + s[j][3];
        }
        rs0 += __shfl_xor_sync(0xffffffffu, rs0, 1);
        rs0 += __shfl_xor_sync(0xffffffffu, rs0, 2);
        rs1 += __shfl_xor_sync(0xffffffffu, rs1, 1);
        rs1 += __shfl_xor_sync(0xffffffffu, rs1, 2);

        l0 = l0 * c0 + rs0;
        l1 = l1 * c1 + rs1;
#pragma unroll
        for (int j = 0; j < 8; j++) {
            o[j][0] *= c0; o[j][1] *= c0;
            o[j][2] *= c1; o[j][3] *= c1;
        }

        // ---- O += P V : single-term fp16 ----
#pragma unroll
        for (int kk = 0; kk < 4; kk++) {
            uint32_t ph[4];
            ph[0] = packh2(s[2 * kk][0],     s[2 * kk][1]);
            ph[1] = packh2(s[2 * kk][2],     s[2 * kk][3]);
            ph[2] = packh2(s[2 * kk + 1][0], s[2 * kk + 1][1]);
            ph[3] = packh2(s[2 * kk + 1][2], s[2 * kk + 1][3]);
#pragma unroll
            for (int jp = 0; jp < 4; jp++) {
                const uint32_t off =
                    (uint32_t)((kk * 16 + a_row) * ATS + jp * 16 + a_col) * 2;
                uint32_t vh0, vh1, vh2, vh3;
                LDSM_X4_T(vh0, vh1, vh2, vh3, kb + OV + off);
                MMA_FP16(o[2 * jp],     ph[0], ph[1], ph[2], ph[3], vh0, vh1);
                MMA_FP16(o[2 * jp + 1], ph[0], ph[1], ph[2], ph[3], vh2, vh3);
            }
        }
    }

    // ---- epilogue ----
    const float i0 = 1.0f / l0, i1 = 1.0f / l1;
    const int grow = b * SEQ + qt * 128 + 16 * wrp + g;
#pragma unroll
    for (int j = 0; j < 8; j++) {
        const int col = h * 64 + j * 8 + 2 * tig;
        *(float2*)(out + (size_t)grow * EMB + col) =
            make_float2(o[j][0] * i0, o[j][1] * i0);
        *(float2*)(out + (size_t)(grow + 8) * EMB + col) =
            make_float2(o[j][2] * i1, o[j][3] * i1);
    }
#undef KV_ISSUE
}

// ---------------------------------------------------------------------------
extern "C" void kernel_launch(void* const* d_in, const int* in_sizes, int n_in,
                              void* d_out, int out_size)
{
    const float* x    = (const float*)d_in[0];
    const float* w    = (const float*)d_in[1];
    const float* Wqkv = (const float*)d_in[2];
    const float* bqkv = (const float*)d_in[3];
    float* out = (float*)d_out;

    cudaFuncSetAttribute(qkv_gemm,
                         cudaFuncAttributeMaxDynamicSharedMemorySize,
                         GEMM_SMEM_BYTES);
    cudaFuncSetAttribute(attn_fp16,
                         cudaFuncAttributeMaxDynamicSharedMemorySize,
                         ATTN_SMEM_BYTES);

    prep_x_kernel<<<MROWS * EMB / 4 / 256, 256>>>((const float4*)x);
    prep_w_kernel<<<EMB * QKVN / 4 / 256, 256>>>((const float4*)Wqkv);
    wprep_kernel<<<(BATCH * SEQ + 255) / 256, 256>>>(w);

    dim3 g1(QKVN / 128, MROWS / 128);            // (24, 32)
    qkv_gemm<<<g1, 256, GEMM_SMEM_BYTES>>>(bqkv);

    dim3 g2(SEQ / 128, NHEAD, BATCH);            // (16, 16, 2)
    attn_fp16<<<g2, 256, ATTN_SMEM_BYTES>>>(out);
}

// round 15
// speedup vs baseline: 1.4910x; 1.1489x over previous
#include <cuda_runtime.h>
#include <cuda_bf16.h>
#include <cuda_fp16.h>
#include <math.h>
#include <stdint.h>

// Problem constants
#define BATCH   2
#define SEQ     2048
#define EMB     1024
#define NHEAD   16
#define QKVN    3072
#define MROWS   4096
#define TINY_F  1.17549435e-38f
#define SCALE_Q 0.125f
#define LOG2E   1.4426950408889634f
#define BIGNEG2 -1.3e16f
#define BIGPOS2  1.3e16f

// Global scratch (all fp16)
__device__ __half g_x_h[(size_t)MROWS * EMB];    // x fp16 (single)
__device__ __half g_w_hi[(size_t)EMB * QKVN];    // (W*32) fp16 hi
__device__ __half g_w_lo[(size_t)EMB * QKVN];    // (W*32) fp16 lo
__device__ __half g_q[(size_t)MROWS * EMB];      // Q fp16   [row][h*64+d]
__device__ __half g_k[(size_t)MROWS * EMB];      // K fp16 (single)
__device__ __half g_v[(size_t)MROWS * EMB];      // V fp16
__device__ float g_wsc[BATCH * SEQ];             // log2-domain scale
__device__ float g_wvl[BATCH * SEQ];             // log2-domain bias

// ---------------------------------------------------------------------------
// PTX helpers
// ---------------------------------------------------------------------------
#define MMA_FP16(c, a0, a1, a2, a3, b0, b1)                                  \
    asm volatile(                                                            \
        "mma.sync.aligned.m16n8k16.row.col.f32.f16.f16.f32 "                 \
        "{%0,%1,%2,%3}, {%4,%5,%6,%7}, {%8,%9}, {%0,%1,%2,%3};"              \
        : "+f"((c)[0]), "+f"((c)[1]), "+f"((c)[2]), "+f"((c)[3])             \
        : "r"(a0), "r"(a1), "r"(a2), "r"(a3), "r"(b0), "r"(b1))

#define LDSM_X4(r0, r1, r2, r3, a)                                           \
    asm volatile("ldmatrix.sync.aligned.m8n8.x4.shared.b16 {%0,%1,%2,%3}, [%4];" \
        : "=r"(r0), "=r"(r1), "=r"(r2), "=r"(r3) : "r"(a))

#define LDSM_X4_T(r0, r1, r2, r3, a)                                         \
    asm volatile("ldmatrix.sync.aligned.m8n8.x4.trans.shared.b16 {%0,%1,%2,%3}, [%4];" \
        : "=r"(r0), "=r"(r1), "=r"(r2), "=r"(r3) : "r"(a))

#define CPA16(dst_u32, src_ptr)                                              \
    asm volatile("cp.async.cg.shared.global [%0], [%1], 16;"                 \
                 :: "r"(dst_u32), "l"(src_ptr))
#define CPA_COMMIT() asm volatile("cp.async.commit_group;")
#define CPA_WAIT1()  asm volatile("cp.async.wait_group 1;")
#define CPA_WAIT0()  asm volatile("cp.async.wait_group 0;")

__device__ __forceinline__ uint32_t packh2(float x, float y)
{
    __half2 h = __floats2half2_rn(x, y);
    return *reinterpret_cast<uint32_t*>(&h);
}

__device__ __forceinline__ void split2h(float x, float y,
                                        uint32_t& hi, uint32_t& lo)
{
    __half2 h = __floats2half2_rn(x, y);
    float rx = x - __half2float(h.x);
    float ry = y - __half2float(h.y);
    __half2 l = __floats2half2_rn(rx, ry);
    hi = *reinterpret_cast<uint32_t*>(&h);
    lo = *reinterpret_cast<uint32_t*>(&l);
}

// ---------------------------------------------------------------------------
// Prep kernels
// ---------------------------------------------------------------------------
__global__ void prep_x_kernel(const float4* __restrict__ in)
{
    int i = blockIdx.x * blockDim.x + threadIdx.x;
    if (i < MROWS * EMB / 4) {
        float4 v = in[i];
        uint2 p;
        p.x = packh2(v.x, v.y);
        p.y = packh2(v.z, v.w);
        ((uint2*)g_x_h)[i] = p;
    }
}

// W stored scaled by 32 (unit-scale -> fp16 lo stays normal);
// GEMM epilogue multiplies the accumulator by exact 1/32.
__global__ void prep_w_kernel(const float4* __restrict__ in)
{
    int i = blockIdx.x * blockDim.x + threadIdx.x;
    if (i < EMB * QKVN / 4) {
        float4 v = in[i];
        uint2 uh, ul;
        split2h(v.x * 32.0f, v.y * 32.0f, uh.x, ul.x);
        split2h(v.z * 32.0f, v.w * 32.0f, uh.y, ul.y);
        ((uint2*)g_w_hi)[i] = uh;
        ((uint2*)g_w_lo)[i] = ul;
    }
}

__global__ void wprep_kernel(const float* __restrict__ w)
{
    int i = blockIdx.x * blockDim.x + threadIdx.x;
    if (i < BATCH * SEQ) {
        const float v = w[i];
        const bool z = (v == 0.0f), on = (v == 1.0f);
        g_wsc[i] = (z || on) ? 0.0f : SCALE_Q * LOG2E;
        g_wvl[i] = z ? BIGNEG2 : (on ? BIGPOS2 : log2f(v + TINY_F));
    }
}

// ---------------------------------------------------------------------------
// Kernel 1: qkv = x @ W + b, asymmetric fp16x2 mma (x single, W hi/lo).
// CTA 128x128, BK=32, 256 threads, __launch_bounds__(256,2) to pin <=128
// regs (R14's pointer-select epilogue hit 150 regs -> 1 CTA/SM cliff).
// 2-buffer ring, issue-before-wait. Epilogue: acc/32 + bias, explicit
// per-region branches (q / k / v fp16).
// ---------------------------------------------------------------------------
#define GA_STR 40
#define GB_STR 136
#define GA_H   (128 * GA_STR)                  // 5120 halves
#define GB_H   (32 * GB_STR)                   // 4352 halves
#define GBUF_H (GA_H + 2 * GB_H)               // 13824 halves / buffer
#define GEMM_SMEM_BYTES (2 * GBUF_H * 2)       // 55296

__global__ void __launch_bounds__(256, 2)
qkv_gemm(const float* __restrict__ bias)
{
    extern __shared__ __half sh[];
    const uint32_t sbase = (uint32_t)__cvta_generic_to_shared(sh);

    const int tid  = threadIdx.x;
    const int lane = tid & 31, wid = tid >> 5;
    const int g = lane >> 2, tig = lane & 3;
    const int wr = wid >> 1, wc = wid & 1;
    const int bn = blockIdx.x * 128, bm = blockIdx.y * 128;

    const uint32_t OA  = 0;
    const uint32_t OBh = GA_H * 2, OBl = (GA_H + GB_H) * 2;
    const uint32_t BUFB = GBUF_H * 2;

    float acc[2][8][4];
#pragma unroll
    for (int mt = 0; mt < 2; mt++)
#pragma unroll
        for (int j = 0; j < 8; j++)
#pragma unroll
            for (int q = 0; q < 4; q++) acc[mt][j][q] = 0.0f;

    const int a_row = (lane & 7) + 8 * ((lane >> 3) & 1);
    const int a_col = 8 * (lane >> 4);
    const int b_row = lane & 15;
    const int b_col = 8 * (lane >> 4);

#define GEMM_ISSUE(buf, kt)                                                  \
    do {                                                                     \
        const uint32_t sb = sbase + (buf) * BUFB;                            \
        _Pragma("unroll")                                                    \
        for (int i = 0; i < 2; i++) {                                        \
            int ch = tid + 256 * i;                                          \
            int r = ch >> 2, sg = ch & 3;                                    \
            size_t go = (size_t)(bm + r) * EMB + (kt) * 32 + sg * 8;         \
            CPA16(sb + OA + (uint32_t)(r * GA_STR + sg * 8) * 2, g_x_h + go);\
        }                                                                    \
        _Pragma("unroll")                                                    \
        for (int i = 0; i < 2; i++) {                                        \
            int ch = tid + 256 * i;                                          \
            int r = ch >> 4, sg = ch & 15;                                   \
            size_t go = (size_t)((kt) * 32 + r) * QKVN + bn + sg * 8;        \
            uint32_t d = sb + (uint32_t)(r * GB_STR + sg * 8) * 2;           \
            CPA16(d + OBh, g_w_hi + go);                                     \
            CPA16(d + OBl, g_w_lo + go);                                     \
        }                                                                    \
    } while (0)

    GEMM_ISSUE(0, 0);
    CPA_COMMIT();

    for (int kt = 0; kt < 32; kt++) {
        const int buf = kt & 1;
        if (kt < 31) {
            GEMM_ISSUE(buf ^ 1, kt + 1);
            CPA_COMMIT();
            CPA_WAIT1();
        } else {
            CPA_WAIT0();
        }
        __syncthreads();

        const uint32_t sb = sbase + buf * BUFB;
#pragma unroll
        for (int ks = 0; ks < 2; ks++) {
            const int k0 = ks * 16;
            uint32_t ah[2][4];
#pragma unroll
            for (int mt = 0; mt < 2; mt++) {
                const uint32_t off =
                    (uint32_t)((wr * 32 + mt * 16 + a_row) * GA_STR + k0 + a_col) * 2;
                LDSM_X4(ah[mt][0], ah[mt][1], ah[mt][2], ah[mt][3], sb + OA + off);
            }
#pragma unroll
            for (int jp = 0; jp < 4; jp++) {
                const uint32_t off =
                    (uint32_t)((k0 + b_row) * GB_STR + wc * 64 + jp * 16 + b_col) * 2;
                uint32_t bh0, bh1, bh2, bh3, bl0, bl1, bl2, bl3;
                LDSM_X4_T(bh0, bh1, bh2, bh3, sb + OBh + off);
                LDSM_X4_T(bl0, bl1, bl2, bl3, sb + OBl + off);
                MMA_FP16(acc[0][2 * jp],     ah[0][0], ah[0][1], ah[0][2], ah[0][3], bh0, bh1);
                MMA_FP16(acc[1][2 * jp],     ah[1][0], ah[1][1], ah[1][2], ah[1][3], bh0, bh1);
                MMA_FP16(acc[0][2 * jp + 1], ah[0][0], ah[0][1], ah[0][2], ah[0][3], bh2, bh3);
                MMA_FP16(acc[1][2 * jp + 1], ah[1][0], ah[1][1], ah[1][2], ah[1][3], bh2, bh3);
                MMA_FP16(acc[0][2 * jp],     ah[0][0], ah[0][1], ah[0][2], ah[0][3], bl0, bl1);
                MMA_FP16(acc[1][2 * jp],     ah[1][0], ah[1][1], ah[1][2], ah[1][3], bl0, bl1);
                MMA_FP16(acc[0][2 * jp + 1], ah[0][0], ah[0][1], ah[0][2], ah[0][3], bl2, bl3);
                MMA_FP16(acc[1][2 * jp + 1], ah[1][0], ah[1][1], ah[1][2], ah[1][3], bl2, bl3);
            }
        }
        __syncthreads();
    }

    // Epilogue: rescale (W stored x32), add bias, explicit per-region routing.
#pragma unroll
    for (int mt = 0; mt < 2; mt++) {
        const int row0 = bm + wr * 32 + mt * 16 + g;
#pragma unroll
        for (int j = 0; j < 8; j++) {
            const int col = bn + wc * 64 + j * 8 + 2 * tig;
            const float2 bb = *(const float2*)(bias + col);
            const float v00 = acc[mt][j][0] * 0.03125f + bb.x;
            const float v01 = acc[mt][j][1] * 0.03125f + bb.y;
            const float v10 = acc[mt][j][2] * 0.03125f + bb.x;
            const float v11 = acc[mt][j][3] * 0.03125f + bb.y;
            const uint32_t p0 = packh2(v00, v01);
            const uint32_t p1 = packh2(v10, v11);
            const int cm = col % 192;
            const int head = col / 192;
            if (cm < 64) {
                const size_t o0 = (size_t)row0 * EMB + head * 64 + cm;
                *(uint32_t*)(g_q + o0)           = p0;
                *(uint32_t*)(g_q + o0 + 8 * EMB) = p1;
            } else if (cm < 128) {
                const size_t o0 = (size_t)row0 * EMB + head * 64 + (cm - 64);
                *(uint32_t*)(g_k + o0)           = p0;
                *(uint32_t*)(g_k + o0 + 8 * EMB) = p1;
            } else {
                const size_t o0 = (size_t)row0 * EMB + head * 64 + (cm - 128);
                *(uint32_t*)(g_v + o0)           = p0;
                *(uint32_t*)(g_v + o0 + 8 * EMB) = p1;
            }
        }
    }
#undef GEMM_ISSUE
}

// ---------------------------------------------------------------------------
// Kernel 2: flash attention (unchanged from R14). Grid (S/128, H, B),
// 256 threads, 2 CTAs/SM. S = q·k single fp16; PV single-term fp16.
// BQ=128, BN=64, 2-slot KV ring, exp2 softmax. smem 55296.
// ---------------------------------------------------------------------------
#define ATS      72
#define QTILE_B  (128 * ATS * 2)               // 18432
#define KT64_B   (64 * ATS * 2)                // 9216
#define KVBASE   QTILE_B
#define SLOT_B   (2 * KT64_B)                  // 18432 (K, V)
#define OK       0
#define OV       KT64_B
#define ATTN_SMEM_BYTES (KVBASE + 2 * SLOT_B)  // 55296 -> 2 CTAs/SM
#define NKT      (SEQ / 64)                    // 32

__global__ void __launch_bounds__(256, 2)
attn_fp16(float* __restrict__ out)
{
    extern __shared__ char shb[];
    const uint32_t sb = (uint32_t)__cvta_generic_to_shared(shb);

    const int tid  = threadIdx.x;
    const int lane = tid & 31, wrp = tid >> 5;
    const int g = lane >> 2, tig = lane & 3;
    const int qt = blockIdx.x, h = blockIdx.y, b = blockIdx.z;

    const int a_row = (lane & 7) + 8 * ((lane >> 3) & 1);
    const int a_col = 8 * (lane >> 4);
    const int k_row = (lane & 7) + 8 * (lane >> 4);
    const int k_col = 8 * ((lane >> 3) & 1);

#define KV_ISSUE(slot, tt)                                                   \
    do {                                                                     \
        const uint32_t kbase = sb + KVBASE + (uint32_t)(slot) * SLOT_B;      \
        _Pragma("unroll")                                                    \
        for (int i = 0; i < 2; i++) {                                        \
            int ch = tid + 256 * i;                                          \
            int r = ch >> 3, sg = ch & 7;                                    \
            size_t go = (size_t)(b * SEQ + (tt) * 64 + r) * EMB + h * 64 + sg * 8; \
            uint32_t d = (uint32_t)(r * ATS + sg * 8) * 2;                   \
            CPA16(kbase + OK + d, g_k + go);                                 \
            CPA16(kbase + OV + d, g_v + go);                                 \
        }                                                                    \
        CPA_COMMIT();                                                        \
    } while (0)

    // ---- prologue: Q (group 0), KV tile 0 (group 1) ----
#pragma unroll
    for (int i = 0; i < 4; i++) {
        const int ch = tid + 256 * i;
        const int r = ch >> 3, sg = ch & 7;
        const size_t go = (size_t)(b * SEQ + qt * 128 + r) * EMB + h * 64 + sg * 8;
        CPA16(sb + (uint32_t)(r * ATS + sg * 8) * 2, g_q + go);
    }
    CPA_COMMIT();
    KV_ISSUE(0, 0);
    CPA_WAIT1();           // Q landed
    __syncthreads();

    // Q fragments (fp16, loop invariant)
    uint32_t qh[4][4];
#pragma unroll
    for (int kk = 0; kk < 4; kk++) {
        const uint32_t off =
            (uint32_t)((16 * wrp + a_row) * ATS + kk * 16 + a_col) * 2;
        LDSM_X4(qh[kk][0], qh[kk][1], qh[kk][2], qh[kk][3], sb + off);
    }

    float m0 = -1e30f, m1 = -1e30f, l0 = 0.0f, l1 = 0.0f;
    float o[8][4];
#pragma unroll
    for (int j = 0; j < 8; j++)
        o[j][0] = o[j][1] = o[j][2] = o[j][3] = 0.0f;

    const float* wscp = g_wsc + b * SEQ;
    const float* wvlp = g_wvl + b * SEQ;

    for (int t = 0; t < NKT; t++) {
        const int slot = t & 1;
        CPA_WAIT0();
        __syncthreads();

        if (t + 1 < NKT)
            KV_ISSUE(slot ^ 1, t + 1);

        const uint32_t kb = sb + KVBASE + (uint32_t)slot * SLOT_B;

        // ---- S = q k^T : single fp16, 16 q-rows x 64 keys per warp ----
        float s[8][4];
#pragma unroll
        for (int j = 0; j < 8; j++)
            s[j][0] = s[j][1] = s[j][2] = s[j][3] = 0.0f;

#pragma unroll
        for (int kk = 0; kk < 4; kk++) {
#pragma unroll
            for (int jp = 0; jp < 4; jp++) {
                const uint32_t off =
                    (uint32_t)((jp * 16 + k_row) * ATS + kk * 16 + k_col) * 2;
                uint32_t kh0, kh1, kh2, kh3;
                LDSM_X4(kh0, kh1, kh2, kh3, kb + OK + off);
                MMA_FP16(s[2 * jp],     qh[kk][0], qh[kk][1], qh[kk][2], qh[kk][3], kh0, kh1);
                MMA_FP16(s[2 * jp + 1], qh[kk][0], qh[kk][1], qh[kk][2], qh[kk][3], kh2, kh3);
            }
        }

        // ---- logit transform (log2 domain) + row max ----
        const int wbase = t * 64;
        float mx0 = -1e30f, mx1 = -1e30f;
#pragma unroll
        for (int j = 0; j < 8; j++) {
            const float2 ws = *(const float2*)&wscp[wbase + j * 8 + 2 * tig];
            const float2 wv = *(const float2*)&wvlp[wbase + j * 8 + 2 * tig];
            s[j][0] = fmaf(s[j][0], ws.x, wv.x);
            s[j][1] = fmaf(s[j][1], ws.y, wv.y);
            s[j][2] = fmaf(s[j][2], ws.x, wv.x);
            s[j][3] = fmaf(s[j][3], ws.y, wv.y);
            mx0 = fmaxf(mx0, fmaxf(s[j][0], s[j][1]));
            mx1 = fmaxf(mx1, fmaxf(s[j][2], s[j][3]));
        }
        mx0 = fmaxf(mx0, __shfl_xor_sync(0xffffffffu, mx0, 1));
        mx0 = fmaxf(mx0, __shfl_xor_sync(0xffffffffu, mx0, 2));
        mx1 = fmaxf(mx1, __shfl_xor_sync(0xffffffffu, mx1, 1));
        mx1 = fmaxf(mx1, __shfl_xor_sync(0xffffffffu, mx1, 2));

        const float mn0 = fmaxf(m0, mx0), mn1 = fmaxf(m1, mx1);
        const float c0 = exp2f(m0 - mn0), c1 = exp2f(m1 - mn1);
        m0 = mn0; m1 = mn1;

        float rs0 = 0.0f, rs1 = 0.0f;
#pragma unroll
        for (int j = 0; j < 8; j++) {
            s[j][0] = exp2f(s[j][0] - m0);
            s[j][1] = exp2f(s[j][1] - m0);
            s[j][2] = exp2f(s[j][2] - m1);
            s[j][3] = exp2f(s[j][3] - m1);
            rs0 += s[j][0] + s[j][1];
            rs1 += s[j][2] + s[j][3];
        }
        rs0 += __shfl_xor_sync(0xffffffffu, rs0, 1);
        rs0 += __shfl_xor_sync(0xffffffffu, rs0, 2);
        rs1 += __shfl_xor_sync(0xffffffffu, rs1, 1);
        rs1 += __shfl_xor_sync(0xffffffffu, rs1, 2);

        l0 = l0 * c0 + rs0;
        l1 = l1 * c1 + rs1;
#pragma unroll
        for (int j = 0; j < 8; j++) {
            o[j][0] *= c0; o[j][1] *= c0;
            o[j][2] *= c1; o[j][3] *= c1;
        }

        // ---- O += P V : single-term fp16 ----
#pragma unroll
        for (int kk = 0; kk < 4; kk++) {
            uint32_t ph[4];
            ph[0] = packh2(s[2 * kk][0],     s[2 * kk][1]);
            ph[1] = packh2(s[2 * kk][2],     s[2 * kk][3]);
            ph[2] = packh2(s[2 * kk + 1][0], s[2 * kk + 1][1]);
            ph[3] = packh2(s[2 * kk + 1][2], s[2 * kk + 1][3]);
#pragma unroll
            for (int jp = 0; jp < 4; jp++) {
                const uint32_t off =
                    (uint32_t)((kk * 16 + a_row) * ATS + jp * 16 + a_col) * 2;
                uint32_t vh0, vh1, vh2, vh3;
                LDSM_X4_T(vh0, vh1, vh2, vh3, kb + OV + off);
                MMA_FP16(o[2 * jp],     ph[0], ph[1], ph[2], ph[3], vh0, vh1);
                MMA_FP16(o[2 * jp + 1], ph[0], ph[1], ph[2], ph[3], vh2, vh3);
            }
        }
    }

    // ---- epilogue ----
    const float i0 = 1.0f / l0, i1 = 1.0f / l1;
    const int grow = b * SEQ + qt * 128 + 16 * wrp + g;
#pragma unroll
    for (int j = 0; j < 8; j++) {
        const int col = h * 64 + j * 8 + 2 * tig;
        *(float2*)(out + (size_t)grow * EMB + col) =
            make_float2(o[j][0] * i0, o[j][1] * i0);
        *(float2*)(out + (size_t)(grow + 8) * EMB + col) =
            make_float2(o[j][2] * i1, o[j][3] * i1);
    }
#undef KV_ISSUE
}

// ---------------------------------------------------------------------------
extern "C" void kernel_launch(void* const* d_in, const int* in_sizes, int n_in,
                              void* d_out, int out_size)
{
    const float* x    = (const float*)d_in[0];
    const float* w    = (const float*)d_in[1];
    const float* Wqkv = (const float*)d_in[2];
    const float* bqkv = (const float*)d_in[3];
    float* out = (float*)d_out;

    cudaFuncSetAttribute(qkv_gemm,
                         cudaFuncAttributeMaxDynamicSharedMemorySize,
                         GEMM_SMEM_BYTES);
    cudaFuncSetAttribute(attn_fp16,
                         cudaFuncAttributeMaxDynamicSharedMemorySize,
                         ATTN_SMEM_BYTES);

    prep_x_kernel<<<MROWS * EMB / 4 / 256, 256>>>((const float4*)x);
    prep_w_kernel<<<EMB * QKVN / 4 / 256, 256>>>((const float4*)Wqkv);
    wprep_kernel<<<(BATCH * SEQ + 255) / 256, 256>>>(w);

    dim3 g1(QKVN / 128, MROWS / 128);            // (24, 32)
    qkv_gemm<<<g1, 256, GEMM_SMEM_BYTES>>>(bqkv);

    dim3 g2(SEQ / 128, NHEAD, BATCH);            // (16, 16, 2)
    attn_fp16<<<g2, 256, ATTN_SMEM_BYTES>>>(out);
}

// round 16
// speedup vs baseline: 1.8467x; 1.2386x over previous
#include <cuda_runtime.h>
#include <cuda_bf16.h>
#include <cuda_fp16.h>
#include <math.h>
#include <stdint.h>

// Problem constants
#define BATCH   2
#define SEQ     2048
#define EMB     1024
#define NHEAD   16
#define QKVN    3072
#define MROWS   4096
#define TINY_F  1.17549435e-38f
#define SCALE_Q 0.125f
#define LOG2E   1.4426950408889634f
#define BIGNEG2 -1.3e16f
#define BIGPOS2  1.3e16f

// Global scratch (all fp16)
__device__ __half g_x_h[(size_t)MROWS * EMB];    // x fp16
__device__ __half g_w_h[(size_t)EMB * QKVN];     // W fp16 (single)
__device__ __half g_q[(size_t)MROWS * EMB];      // Q fp16   [row][h*64+d]
__device__ __half g_k[(size_t)MROWS * EMB];      // K fp16
__device__ __half g_v[(size_t)MROWS * EMB];      // V fp16
__device__ float g_wsc[BATCH * SEQ];             // log2-domain scale
__device__ float g_wvl[BATCH * SEQ];             // log2-domain bias

// ---------------------------------------------------------------------------
// PTX helpers
// ---------------------------------------------------------------------------
#define MMA_FP16(c, a0, a1, a2, a3, b0, b1)                                  \
    asm volatile(                                                            \
        "mma.sync.aligned.m16n8k16.row.col.f32.f16.f16.f32 "                 \
        "{%0,%1,%2,%3}, {%4,%5,%6,%7}, {%8,%9}, {%0,%1,%2,%3};"              \
        : "+f"((c)[0]), "+f"((c)[1]), "+f"((c)[2]), "+f"((c)[3])             \
        : "r"(a0), "r"(a1), "r"(a2), "r"(a3), "r"(b0), "r"(b1))

#define LDSM_X4(r0, r1, r2, r3, a)                                           \
    asm volatile("ldmatrix.sync.aligned.m8n8.x4.shared.b16 {%0,%1,%2,%3}, [%4];" \
        : "=r"(r0), "=r"(r1), "=r"(r2), "=r"(r3) : "r"(a))

#define LDSM_X4_T(r0, r1, r2, r3, a)                                         \
    asm volatile("ldmatrix.sync.aligned.m8n8.x4.trans.shared.b16 {%0,%1,%2,%3}, [%4];" \
        : "=r"(r0), "=r"(r1), "=r"(r2), "=r"(r3) : "r"(a))

#define CPA16(dst_u32, src_ptr)                                              \
    asm volatile("cp.async.cg.shared.global [%0], [%1], 16;"                 \
                 :: "r"(dst_u32), "l"(src_ptr))
#define CPA_COMMIT() asm volatile("cp.async.commit_group;")
#define CPA_WAIT1()  asm volatile("cp.async.wait_group 1;")
#define CPA_WAIT0()  asm volatile("cp.async.wait_group 0;")

__device__ __forceinline__ uint32_t packh2(float x, float y)
{
    __half2 h = __floats2half2_rn(x, y);
    return *reinterpret_cast<uint32_t*>(&h);
}

// ---------------------------------------------------------------------------
// Prep kernels
// ---------------------------------------------------------------------------
__global__ void prep_x_kernel(const float4* __restrict__ in)
{
    int i = blockIdx.x * blockDim.x + threadIdx.x;
    if (i < MROWS * EMB / 4) {
        float4 v = in[i];
        uint2 p;
        p.x = packh2(v.x, v.y);
        p.y = packh2(v.z, v.w);
        ((uint2*)g_x_h)[i] = p;
    }
}

__global__ void prep_w_kernel(const float4* __restrict__ in)
{
    int i = blockIdx.x * blockDim.x + threadIdx.x;
    if (i < EMB * QKVN / 4) {
        float4 v = in[i];
        uint2 p;
        p.x = packh2(v.x, v.y);
        p.y = packh2(v.z, v.w);
        ((uint2*)g_w_h)[i] = p;
    }
}

__global__ void wprep_kernel(const float* __restrict__ w)
{
    int i = blockIdx.x * blockDim.x + threadIdx.x;
    if (i < BATCH * SEQ) {
        const float v = w[i];
        const bool z = (v == 0.0f), on = (v == 1.0f);
        g_wsc[i] = (z || on) ? 0.0f : SCALE_Q * LOG2E;
        g_wvl[i] = z ? BIGNEG2 : (on ? BIGPOS2 : log2f(v + TINY_F));
    }
}

// ---------------------------------------------------------------------------
// Kernel 1: qkv = x @ W + b, single-fp16 x single-fp16 mma.
// CTA 128x128, BK=32, 256 threads, __launch_bounds__(256,2).
// 2-buffer ring, issue-before-wait. Epilogue: bias, route to q / k / v.
// ---------------------------------------------------------------------------
#define GA_STR 40
#define GB_STR 136
#define GA_H   (128 * GA_STR)                  // 5120 halves
#define GB_H   (32 * GB_STR)                   // 4352 halves
#define GBUF_H (GA_H + GB_H)                   // 9472 halves / buffer
#define GEMM_SMEM_BYTES (2 * GBUF_H * 2)       // 37888

__global__ void __launch_bounds__(256, 2)
qkv_gemm(const float* __restrict__ bias)
{
    extern __shared__ __half sh[];
    const uint32_t sbase = (uint32_t)__cvta_generic_to_shared(sh);

    const int tid  = threadIdx.x;
    const int lane = tid & 31, wid = tid >> 5;
    const int g = lane >> 2, tig = lane & 3;
    const int wr = wid >> 1, wc = wid & 1;
    const int bn = blockIdx.x * 128, bm = blockIdx.y * 128;

    const uint32_t OA = 0;
    const uint32_t OB = GA_H * 2;
    const uint32_t BUFB = GBUF_H * 2;

    float acc[2][8][4];
#pragma unroll
    for (int mt = 0; mt < 2; mt++)
#pragma unroll
        for (int j = 0; j < 8; j++)
#pragma unroll
            for (int q = 0; q < 4; q++) acc[mt][j][q] = 0.0f;

    const int a_row = (lane & 7) + 8 * ((lane >> 3) & 1);
    const int a_col = 8 * (lane >> 4);
    const int b_row = lane & 15;
    const int b_col = 8 * (lane >> 4);

    // A tile: 512 chunks -> 2/thread. B tile: 512 chunks -> 2/thread.
#define GEMM_ISSUE(buf, kt)                                                  \
    do {                                                                     \
        const uint32_t sb = sbase + (buf) * BUFB;                            \
        _Pragma("unroll")                                                    \
        for (int i = 0; i < 2; i++) {                                        \
            int ch = tid + 256 * i;                                          \
            int r = ch >> 2, sg = ch & 3;                                    \
            size_t go = (size_t)(bm + r) * EMB + (kt) * 32 + sg * 8;         \
            CPA16(sb + OA + (uint32_t)(r * GA_STR + sg * 8) * 2, g_x_h + go);\
        }                                                                    \
        _Pragma("unroll")                                                    \
        for (int i = 0; i < 2; i++) {                                        \
            int ch = tid + 256 * i;                                          \
            int r = ch >> 4, sg = ch & 15;                                   \
            size_t go = (size_t)((kt) * 32 + r) * QKVN + bn + sg * 8;        \
            CPA16(sb + OB + (uint32_t)(r * GB_STR + sg * 8) * 2, g_w_h + go);\
        }                                                                    \
    } while (0)

    GEMM_ISSUE(0, 0);
    CPA_COMMIT();

    for (int kt = 0; kt < 32; kt++) {
        const int buf = kt & 1;
        if (kt < 31) {
            GEMM_ISSUE(buf ^ 1, kt + 1);
            CPA_COMMIT();
            CPA_WAIT1();
        } else {
            CPA_WAIT0();
        }
        __syncthreads();

        const uint32_t sb = sbase + buf * BUFB;
#pragma unroll
        for (int ks = 0; ks < 2; ks++) {
            const int k0 = ks * 16;
            uint32_t ah[2][4];
#pragma unroll
            for (int mt = 0; mt < 2; mt++) {
                const uint32_t off =
                    (uint32_t)((wr * 32 + mt * 16 + a_row) * GA_STR + k0 + a_col) * 2;
                LDSM_X4(ah[mt][0], ah[mt][1], ah[mt][2], ah[mt][3], sb + OA + off);
            }
#pragma unroll
            for (int jp = 0; jp < 4; jp++) {
                const uint32_t off =
                    (uint32_t)((k0 + b_row) * GB_STR + wc * 64 + jp * 16 + b_col) * 2;
                uint32_t bh0, bh1, bh2, bh3;
                LDSM_X4_T(bh0, bh1, bh2, bh3, sb + OB + off);
                MMA_FP16(acc[0][2 * jp],     ah[0][0], ah[0][1], ah[0][2], ah[0][3], bh0, bh1);
                MMA_FP16(acc[1][2 * jp],     ah[1][0], ah[1][1], ah[1][2], ah[1][3], bh0, bh1);
                MMA_FP16(acc[0][2 * jp + 1], ah[0][0], ah[0][1], ah[0][2], ah[0][3], bh2, bh3);
                MMA_FP16(acc[1][2 * jp + 1], ah[1][0], ah[1][1], ah[1][2], ah[1][3], bh2, bh3);
            }
        }
        __syncthreads();
    }

    // Epilogue: add bias, route per head region (q/k/v) as fp16.
#pragma unroll
    for (int mt = 0; mt < 2; mt++) {
        const int row0 = bm + wr * 32 + mt * 16 + g;
#pragma unroll
        for (int j = 0; j < 8; j++) {
            const int col = bn + wc * 64 + j * 8 + 2 * tig;
            const float2 bb = *(const float2*)(bias + col);
            const uint32_t p0 = packh2(acc[mt][j][0] + bb.x, acc[mt][j][1] + bb.y);
            const uint32_t p1 = packh2(acc[mt][j][2] + bb.x, acc[mt][j][3] + bb.y);
            const int cm = col % 192;
            const int head = col / 192;
            if (cm < 64) {
                const size_t o0 = (size_t)row0 * EMB + head * 64 + cm;
                *(uint32_t*)(g_q + o0)           = p0;
                *(uint32_t*)(g_q + o0 + 8 * EMB) = p1;
            } else if (cm < 128) {
                const size_t o0 = (size_t)row0 * EMB + head * 64 + (cm - 64);
                *(uint32_t*)(g_k + o0)           = p0;
                *(uint32_t*)(g_k + o0 + 8 * EMB) = p1;
            } else {
                const size_t o0 = (size_t)row0 * EMB + head * 64 + (cm - 128);
                *(uint32_t*)(g_v + o0)           = p0;
                *(uint32_t*)(g_v + o0 + 8 * EMB) = p1;
            }
        }
    }
#undef GEMM_ISSUE
}

// ---------------------------------------------------------------------------
// Kernel 2: flash attention (unchanged from R15). Grid (S/128, H, B),
// 256 threads, 2 CTAs/SM. S = q·k single fp16; PV single-term fp16.
// BQ=128, BN=64, 2-slot KV ring, exp2 softmax. smem 55296.
// ---------------------------------------------------------------------------
#define ATS      72
#define QTILE_B  (128 * ATS * 2)               // 18432
#define KT64_B   (64 * ATS * 2)                // 9216
#define KVBASE   QTILE_B
#define SLOT_B   (2 * KT64_B)                  // 18432 (K, V)
#define OK       0
#define OV       KT64_B
#define ATTN_SMEM_BYTES (KVBASE + 2 * SLOT_B)  // 55296 -> 2 CTAs/SM
#define NKT      (SEQ / 64)                    // 32

__global__ void __launch_bounds__(256, 2)
attn_fp16(float* __restrict__ out)
{
    extern __shared__ char shb[];
    const uint32_t sb = (uint32_t)__cvta_generic_to_shared(shb);

    const int tid  = threadIdx.x;
    const int lane = tid & 31, wrp = tid >> 5;
    const int g = lane >> 2, tig = lane & 3;
    const int qt = blockIdx.x, h = blockIdx.y, b = blockIdx.z;

    const int a_row = (lane & 7) + 8 * ((lane >> 3) & 1);
    const int a_col = 8 * (lane >> 4);
    const int k_row = (lane & 7) + 8 * (lane >> 4);
    const int k_col = 8 * ((lane >> 3) & 1);

#define KV_ISSUE(slot, tt)                                                   \
    do {                                                                     \
        const uint32_t kbase = sb + KVBASE + (uint32_t)(slot) * SLOT_B;      \
        _Pragma("unroll")                                                    \
        for (int i = 0; i < 2; i++) {                                        \
            int ch = tid + 256 * i;                                          \
            int r = ch >> 3, sg = ch & 7;                                    \
            size_t go = (size_t)(b * SEQ + (tt) * 64 + r) * EMB + h * 64 + sg * 8; \
            uint32_t d = (uint32_t)(r * ATS + sg * 8) * 2;                   \
            CPA16(kbase + OK + d, g_k + go);                                 \
            CPA16(kbase + OV + d, g_v + go);                                 \
        }                                                                    \
        CPA_COMMIT();                                                        \
    } while (0)

    // ---- prologue: Q (group 0), KV tile 0 (group 1) ----
#pragma unroll
    for (int i = 0; i < 4; i++) {
        const int ch = tid + 256 * i;
        const int r = ch >> 3, sg = ch & 7;
        const size_t go = (size_t)(b * SEQ + qt * 128 + r) * EMB + h * 64 + sg * 8;
        CPA16(sb + (uint32_t)(r * ATS + sg * 8) * 2, g_q + go);
    }
    CPA_COMMIT();
    KV_ISSUE(0, 0);
    CPA_WAIT1();           // Q landed
    __syncthreads();

    // Q fragments (fp16, loop invariant)
    uint32_t qh[4][4];
#pragma unroll
    for (int kk = 0; kk < 4; kk++) {
        const uint32_t off =
            (uint32_t)((16 * wrp + a_row) * ATS + kk * 16 + a_col) * 2;
        LDSM_X4(qh[kk][0], qh[kk][1], qh[kk][2], qh[kk][3], sb + off);
    }

    float m0 = -1e30f, m1 = -1e30f, l0 = 0.0f, l1 = 0.0f;
    float o[8][4];
#pragma unroll
    for (int j = 0; j < 8; j++)
        o[j][0] = o[j][1] = o[j][2] = o[j][3] = 0.0f;

    const float* wscp = g_wsc + b * SEQ;
    const float* wvlp = g_wvl + b * SEQ;

    for (int t = 0; t < NKT; t++) {
        const int slot = t & 1;
        CPA_WAIT0();
        __syncthreads();

        if (t + 1 < NKT)
            KV_ISSUE(slot ^ 1, t + 1);

        const uint32_t kb = sb + KVBASE + (uint32_t)slot * SLOT_B;

        // ---- S = q k^T : single fp16, 16 q-rows x 64 keys per warp ----
        float s[8][4];
#pragma unroll
        for (int j = 0; j < 8; j++)
            s[j][0] = s[j][1] = s[j][2] = s[j][3] = 0.0f;

#pragma unroll
        for (int kk = 0; kk < 4; kk++) {
#pragma unroll
            for (int jp = 0; jp < 4; jp++) {
                const uint32_t off =
                    (uint32_t)((jp * 16 + k_row) * ATS + kk * 16 + k_col) * 2;
                uint32_t kh0, kh1, kh2, kh3;
                LDSM_X4(kh0, kh1, kh2, kh3, kb + OK + off);
                MMA_FP16(s[2 * jp],     qh[kk][0], qh[kk][1], qh[kk][2], qh[kk][3], kh0, kh1);
                MMA_FP16(s[2 * jp + 1], qh[kk][0], qh[kk][1], qh[kk][2], qh[kk][3], kh2, kh3);
            }
        }

        // ---- logit transform (log2 domain) + row max ----
        const int wbase = t * 64;
        float mx0 = -1e30f, mx1 = -1e30f;
#pragma unroll
        for (int j = 0; j < 8; j++) {
            const float2 ws = *(const float2*)&wscp[wbase + j * 8 + 2 * tig];
            const float2 wv = *(const float2*)&wvlp[wbase + j * 8 + 2 * tig];
            s[j][0] = fmaf(s[j][0], ws.x, wv.x);
            s[j][1] = fmaf(s[j][1], ws.y, wv.y);
            s[j][2] = fmaf(s[j][2], ws.x, wv.x);
            s[j][3] = fmaf(s[j][3], ws.y, wv.y);
            mx0 = fmaxf(mx0, fmaxf(s[j][0], s[j][1]));
            mx1 = fmaxf(mx1, fmaxf(s[j][2], s[j][3]));
        }
        mx0 = fmaxf(mx0, __shfl_xor_sync(0xffffffffu, mx0, 1));
        mx0 = fmaxf(mx0, __shfl_xor_sync(0xffffffffu, mx0, 2));
        mx1 = fmaxf(mx1, __shfl_xor_sync(0xffffffffu, mx1, 1));
        mx1 = fmaxf(mx1, __shfl_xor_sync(0xffffffffu, mx1, 2));

        const float mn0 = fmaxf(m0, mx0), mn1 = fmaxf(m1, mx1);
        const float c0 = exp2f(m0 - mn0), c1 = exp2f(m1 - mn1);
        m0 = mn0; m1 = mn1;

        float rs0 = 0.0f, rs1 = 0.0f;
#pragma unroll
        for (int j = 0; j < 8; j++) {
            s[j][0] = exp2f(s[j][0] - m0);
            s[j][1] = exp2f(s[j][1] - m0);
            s[j][2] = exp2f(s[j][2] - m1);
            s[j][3] = exp2f(s[j][3] - m1);
            rs0 += s[j][0] + s[j][1];
            rs1 += s[j][2] + s[j][3];
        }
        rs0 += __shfl_xor_sync(0xffffffffu, rs0, 1);
        rs0 += __shfl_xor_sync(0xffffffffu, rs0, 2);
        rs1 += __shfl_xor_sync(0xffffffffu, rs1, 1);
        rs1 += __shfl_xor_sync(0xffffffffu, rs1, 2);

        l0 = l0 * c0 + rs0;
        l1 = l1 * c1 + rs1;
#pragma unroll
        for (int j = 0; j < 8; j++) {
            o[j][0] *= c0; o[j][1] *= c0;
            o[j][2] *= c1; o[j][3] *= c1;
        }

        // ---- O += P V : single-term fp16 ----
#pragma unroll
        for (int kk = 0; kk < 4; kk++) {
            uint32_t ph[4];
            ph[0] = packh2(s[2 * kk][0],     s[2 * kk][1]);
            ph[1] = packh2(s[2 * kk][2],     s[2 * kk][3]);
            ph[2] = packh2(s[2 * kk + 1][0], s[2 * kk + 1][1]);
            ph[3] = packh2(s[2 * kk + 1][2], s[2 * kk + 1][3]);
#pragma unroll
            for (int jp = 0; jp < 4; jp++) {
                const uint32_t off =
                    (uint32_t)((kk * 16 + a_row) * ATS + jp * 16 + a_col) * 2;
                uint32_t vh0, vh1, vh2, vh3;
                LDSM_X4_T(vh0, vh1, vh2, vh3, kb + OV + off);
                MMA_FP16(o[2 * jp],     ph[0], ph[1], ph[2], ph[3], vh0, vh1);
                MMA_FP16(o[2 * jp + 1], ph[0], ph[1], ph[2], ph[3], vh2, vh3);
            }
        }
    }

    // ---- epilogue ----
    const float i0 = 1.0f / l0, i1 = 1.0f / l1;
    const int grow = b * SEQ + qt * 128 + 16 * wrp + g;
#pragma unroll
    for (int j = 0; j < 8; j++) {
        const int col = h * 64 + j * 8 + 2 * tig;
        *(float2*)(out + (size_t)grow * EMB + col) =
            make_float2(o[j][0] * i0, o[j][1] * i0);
        *(float2*)(out + (size_t)(grow + 8) * EMB + col) =
            make_float2(o[j][2] * i1, o[j][3] * i1);
    }
#undef KV_ISSUE
}

// ---------------------------------------------------------------------------
extern "C" void kernel_launch(void* const* d_in, const int* in_sizes, int n_in,
                              void* d_out, int out_size)
{
    const float* x    = (const float*)d_in[0];
    const float* w    = (const float*)d_in[1];
    const float* Wqkv = (const float*)d_in[2];
    const float* bqkv = (const float*)d_in[3];
    float* out = (float*)d_out;

    cudaFuncSetAttribute(qkv_gemm,
                         cudaFuncAttributeMaxDynamicSharedMemorySize,
                         GEMM_SMEM_BYTES);
    cudaFuncSetAttribute(attn_fp16,
                         cudaFuncAttributeMaxDynamicSharedMemorySize,
                         ATTN_SMEM_BYTES);

    prep_x_kernel<<<MROWS * EMB / 4 / 256, 256>>>((const float4*)x);
    prep_w_kernel<<<EMB * QKVN / 4 / 256, 256>>>((const float4*)Wqkv);
    wprep_kernel<<<(BATCH * SEQ + 255) / 256, 256>>>(w);

    dim3 g1(QKVN / 128, MROWS / 128);            // (24, 32)
    qkv_gemm<<<g1, 256, GEMM_SMEM_BYTES>>>(bqkv);

    dim3 g2(SEQ / 128, NHEAD, BATCH);            // (16, 16, 2)
    attn_fp16<<<g2, 256, ATTN_SMEM_BYTES>>>(out);
}

// round 17
// speedup vs baseline: 1.8722x; 1.0138x over previous
#include <cuda_runtime.h>
#include <cuda_bf16.h>
#include <cuda_fp16.h>
#include <math.h>
#include <stdint.h>

// Problem constants
#define BATCH   2
#define SEQ     2048
#define EMB     1024
#define NHEAD   16
#define QKVN    3072
#define MROWS   4096
#define TINY_F  1.17549435e-38f
#define SCALE_Q 0.125f
#define LOG2E   1.4426950408889634f
#define BIGNEG2 -1.3e16f
#define BIGPOS2  1.3e16f

// Global scratch (all fp16)
__device__ __half g_x_h[(size_t)MROWS * EMB];    // x fp16
__device__ __half g_w_h[(size_t)EMB * QKVN];     // W fp16
__device__ __half g_q[(size_t)MROWS * EMB];      // Q fp16   [row][h*64+d]
__device__ __half g_k[(size_t)MROWS * EMB];      // K fp16
__device__ __half g_v[(size_t)MROWS * EMB];      // V fp16
__device__ float g_wsc[BATCH * SEQ];             // log2-domain scale
__device__ float g_wvl[BATCH * SEQ];             // log2-domain bias

// ---------------------------------------------------------------------------
// PTX helpers
// ---------------------------------------------------------------------------
#define MMA_FP16(c, a0, a1, a2, a3, b0, b1)                                  \
    asm volatile(                                                            \
        "mma.sync.aligned.m16n8k16.row.col.f32.f16.f16.f32 "                 \
        "{%0,%1,%2,%3}, {%4,%5,%6,%7}, {%8,%9}, {%0,%1,%2,%3};"              \
        : "+f"((c)[0]), "+f"((c)[1]), "+f"((c)[2]), "+f"((c)[3])             \
        : "r"(a0), "r"(a1), "r"(a2), "r"(a3), "r"(b0), "r"(b1))

// fp16 accumulator variant (D/C are 2 x f16x2 regs)
#define MMA_FP16_H(d0, d1, a0, a1, a2, a3, b0, b1)                           \
    asm volatile(                                                            \
        "mma.sync.aligned.m16n8k16.row.col.f16.f16.f16.f16 "                 \
        "{%0,%1}, {%2,%3,%4,%5}, {%6,%7}, {%0,%1};"                          \
        : "+r"(d0), "+r"(d1)                                                 \
        : "r"(a0), "r"(a1), "r"(a2), "r"(a3), "r"(b0), "r"(b1))

#define LDSM_X4(r0, r1, r2, r3, a)                                           \
    asm volatile("ldmatrix.sync.aligned.m8n8.x4.shared.b16 {%0,%1,%2,%3}, [%4];" \
        : "=r"(r0), "=r"(r1), "=r"(r2), "=r"(r3) : "r"(a))

#define LDSM_X4_T(r0, r1, r2, r3, a)                                         \
    asm volatile("ldmatrix.sync.aligned.m8n8.x4.trans.shared.b16 {%0,%1,%2,%3}, [%4];" \
        : "=r"(r0), "=r"(r1), "=r"(r2), "=r"(r3) : "r"(a))

#define CPA16(dst_u32, src_ptr)                                              \
    asm volatile("cp.async.cg.shared.global [%0], [%1], 16;"                 \
                 :: "r"(dst_u32), "l"(src_ptr))
#define CPA_COMMIT() asm volatile("cp.async.commit_group;")
#define CPA_WAIT1()  asm volatile("cp.async.wait_group 1;")
#define CPA_WAIT0()  asm volatile("cp.async.wait_group 0;")

__device__ __forceinline__ uint32_t packh2(float x, float y)
{
    __half2 h = __floats2half2_rn(x, y);
    return *reinterpret_cast<uint32_t*>(&h);
}

// ---------------------------------------------------------------------------
// Prep kernels (x and W conversion merged into one launch)
// ---------------------------------------------------------------------------
#define NX4 (MROWS * EMB / 4)      // 1048576 float4 chunks of x
#define NW4 (EMB * QKVN / 4)       // 786432 float4 chunks of W

__global__ void prep_xw_kernel(const float4* __restrict__ x,
                               const float4* __restrict__ w)
{
    int i = blockIdx.x * blockDim.x + threadIdx.x;
    if (i < NX4) {
        float4 v = x[i];
        uint2 p;
        p.x = packh2(v.x, v.y);
        p.y = packh2(v.z, v.w);
        ((uint2*)g_x_h)[i] = p;
    } else if (i < NX4 + NW4) {
        const int j = i - NX4;
        float4 v = w[j];
        uint2 p;
        p.x = packh2(v.x, v.y);
        p.y = packh2(v.z, v.w);
        ((uint2*)g_w_h)[j] = p;
    }
}

__global__ void wprep_kernel(const float* __restrict__ w)
{
    int i = blockIdx.x * blockDim.x + threadIdx.x;
    if (i < BATCH * SEQ) {
        const float v = w[i];
        const bool z = (v == 0.0f), on = (v == 1.0f);
        g_wsc[i] = (z || on) ? 0.0f : SCALE_Q * LOG2E;
        g_wvl[i] = z ? BIGNEG2 : (on ? BIGPOS2 : log2f(v + TINY_F));
    }
}

// ---------------------------------------------------------------------------
// Kernel 1: qkv = x @ W + b, single-fp16 mma (unchanged from R16).
// ---------------------------------------------------------------------------
#define GA_STR 40
#define GB_STR 136
#define GA_H   (128 * GA_STR)
#define GB_H   (32 * GB_STR)
#define GBUF_H (GA_H + GB_H)
#define GEMM_SMEM_BYTES (2 * GBUF_H * 2)       // 37888

__global__ void __launch_bounds__(256, 2)
qkv_gemm(const float* __restrict__ bias)
{
    extern __shared__ __half sh[];
    const uint32_t sbase = (uint32_t)__cvta_generic_to_shared(sh);

    const int tid  = threadIdx.x;
    const int lane = tid & 31, wid = tid >> 5;
    const int g = lane >> 2, tig = lane & 3;
    const int wr = wid >> 1, wc = wid & 1;
    const int bn = blockIdx.x * 128, bm = blockIdx.y * 128;

    const uint32_t OA = 0;
    const uint32_t OB = GA_H * 2;
    const uint32_t BUFB = GBUF_H * 2;

    float acc[2][8][4];
#pragma unroll
    for (int mt = 0; mt < 2; mt++)
#pragma unroll
        for (int j = 0; j < 8; j++)
#pragma unroll
            for (int q = 0; q < 4; q++) acc[mt][j][q] = 0.0f;

    const int a_row = (lane & 7) + 8 * ((lane >> 3) & 1);
    const int a_col = 8 * (lane >> 4);
    const int b_row = lane & 15;
    const int b_col = 8 * (lane >> 4);

#define GEMM_ISSUE(buf, kt)                                                  \
    do {                                                                     \
        const uint32_t sb = sbase + (buf) * BUFB;                            \
        _Pragma("unroll")                                                    \
        for (int i = 0; i < 2; i++) {                                        \
            int ch = tid + 256 * i;                                          \
            int r = ch >> 2, sg = ch & 3;                                    \
            size_t go = (size_t)(bm + r) * EMB + (kt) * 32 + sg * 8;         \
            CPA16(sb + OA + (uint32_t)(r * GA_STR + sg * 8) * 2, g_x_h + go);\
        }                                                                    \
        _Pragma("unroll")                                                    \
        for (int i = 0; i < 2; i++) {                                        \
            int ch = tid + 256 * i;                                          \
            int r = ch >> 4, sg = ch & 15;                                   \
            size_t go = (size_t)((kt) * 32 + r) * QKVN + bn + sg * 8;        \
            CPA16(sb + OB + (uint32_t)(r * GB_STR + sg * 8) * 2, g_w_h + go);\
        }                                                                    \
    } while (0)

    GEMM_ISSUE(0, 0);
    CPA_COMMIT();

    for (int kt = 0; kt < 32; kt++) {
        const int buf = kt & 1;
        if (kt < 31) {
            GEMM_ISSUE(buf ^ 1, kt + 1);
            CPA_COMMIT();
            CPA_WAIT1();
        } else {
            CPA_WAIT0();
        }
        __syncthreads();

        const uint32_t sb = sbase + buf * BUFB;
#pragma unroll
        for (int ks = 0; ks < 2; ks++) {
            const int k0 = ks * 16;
            uint32_t ah[2][4];
#pragma unroll
            for (int mt = 0; mt < 2; mt++) {
                const uint32_t off =
                    (uint32_t)((wr * 32 + mt * 16 + a_row) * GA_STR + k0 + a_col) * 2;
                LDSM_X4(ah[mt][0], ah[mt][1], ah[mt][2], ah[mt][3], sb + OA + off);
            }
#pragma unroll
            for (int jp = 0; jp < 4; jp++) {
                const uint32_t off =
                    (uint32_t)((k0 + b_row) * GB_STR + wc * 64 + jp * 16 + b_col) * 2;
                uint32_t bh0, bh1, bh2, bh3;
                LDSM_X4_T(bh0, bh1, bh2, bh3, sb + OB + off);
                MMA_FP16(acc[0][2 * jp],     ah[0][0], ah[0][1], ah[0][2], ah[0][3], bh0, bh1);
                MMA_FP16(acc[1][2 * jp],     ah[1][0], ah[1][1], ah[1][2], ah[1][3], bh0, bh1);
                MMA_FP16(acc[0][2 * jp + 1], ah[0][0], ah[0][1], ah[0][2], ah[0][3], bh2, bh3);
                MMA_FP16(acc[1][2 * jp + 1], ah[1][0], ah[1][1], ah[1][2], ah[1][3], bh2, bh3);
            }
        }
        __syncthreads();
    }

    // Epilogue: add bias, route per head region (q/k/v) as fp16.
#pragma unroll
    for (int mt = 0; mt < 2; mt++) {
        const int row0 = bm + wr * 32 + mt * 16 + g;
#pragma unroll
        for (int j = 0; j < 8; j++) {
            const int col = bn + wc * 64 + j * 8 + 2 * tig;
            const float2 bb = *(const float2*)(bias + col);
            const uint32_t p0 = packh2(acc[mt][j][0] + bb.x, acc[mt][j][1] + bb.y);
            const uint32_t p1 = packh2(acc[mt][j][2] + bb.x, acc[mt][j][3] + bb.y);
            const int cm = col % 192;
            const int head = col / 192;
            if (cm < 64) {
                const size_t o0 = (size_t)row0 * EMB + head * 64 + cm;
                *(uint32_t*)(g_q + o0)           = p0;
                *(uint32_t*)(g_q + o0 + 8 * EMB) = p1;
            } else if (cm < 128) {
                const size_t o0 = (size_t)row0 * EMB + head * 64 + (cm - 64);
                *(uint32_t*)(g_k + o0)           = p0;
                *(uint32_t*)(g_k + o0 + 8 * EMB) = p1;
            } else {
                const size_t o0 = (size_t)row0 * EMB + head * 64 + (cm - 128);
                *(uint32_t*)(g_v + o0)           = p0;
                *(uint32_t*)(g_v + o0 + 8 * EMB) = p1;
            }
        }
    }
#undef GEMM_ISSUE
}

// ---------------------------------------------------------------------------
// Kernel 2: flash attention. S fp32-acc fp16 mma (unchanged); PV uses fp16
// accumulators per 64-key tile (4 chained MMAs), promoted into fp32 o each
// tile: o = o*c + tile. Grid (S/128, H, B), 256 threads, 2 CTAs/SM.
// ---------------------------------------------------------------------------
#define ATS      72
#define QTILE_B  (128 * ATS * 2)
#define KT64_B   (64 * ATS * 2)
#define KVBASE   QTILE_B
#define SLOT_B   (2 * KT64_B)
#define OK       0
#define OV       KT64_B
#define ATTN_SMEM_BYTES (KVBASE + 2 * SLOT_B)  // 55296
#define NKT      (SEQ / 64)

__global__ void __launch_bounds__(256, 2)
attn_fp16(float* __restrict__ out)
{
    extern __shared__ char shb[];
    const uint32_t sb = (uint32_t)__cvta_generic_to_shared(shb);

    const int tid  = threadIdx.x;
    const int lane = tid & 31, wrp = tid >> 5;
    const int g = lane >> 2, tig = lane & 3;
    const int qt = blockIdx.x, h = blockIdx.y, b = blockIdx.z;

    const int a_row = (lane & 7) + 8 * ((lane >> 3) & 1);
    const int a_col = 8 * (lane >> 4);
    const int k_row = (lane & 7) + 8 * (lane >> 4);
    const int k_col = 8 * ((lane >> 3) & 1);

#define KV_ISSUE(slot, tt)                                                   \
    do {                                                                     \
        const uint32_t kbase = sb + KVBASE + (uint32_t)(slot) * SLOT_B;      \
        _Pragma("unroll")                                                    \
        for (int i = 0; i < 2; i++) {                                        \
            int ch = tid + 256 * i;                                          \
            int r = ch >> 3, sg = ch & 7;                                    \
            size_t go = (size_t)(b * SEQ + (tt) * 64 + r) * EMB + h * 64 + sg * 8; \
            uint32_t d = (uint32_t)(r * ATS + sg * 8) * 2;                   \
            CPA16(kbase + OK + d, g_k + go);                                 \
            CPA16(kbase + OV + d, g_v + go);                                 \
        }                                                                    \
        CPA_COMMIT();                                                        \
    } while (0)

    // ---- prologue ----
#pragma unroll
    for (int i = 0; i < 4; i++) {
        const int ch = tid + 256 * i;
        const int r = ch >> 3, sg = ch & 7;
        const size_t go = (size_t)(b * SEQ + qt * 128 + r) * EMB + h * 64 + sg * 8;
        CPA16(sb + (uint32_t)(r * ATS + sg * 8) * 2, g_q + go);
    }
    CPA_COMMIT();
    KV_ISSUE(0, 0);
    CPA_WAIT1();
    __syncthreads();

    uint32_t qh[4][4];
#pragma unroll
    for (int kk = 0; kk < 4; kk++) {
        const uint32_t off =
            (uint32_t)((16 * wrp + a_row) * ATS + kk * 16 + a_col) * 2;
        LDSM_X4(qh[kk][0], qh[kk][1], qh[kk][2], qh[kk][3], sb + off);
    }

    float m0 = -1e30f, m1 = -1e30f, l0 = 0.0f, l1 = 0.0f;
    float o[8][4];
#pragma unroll
    for (int j = 0; j < 8; j++)
        o[j][0] = o[j][1] = o[j][2] = o[j][3] = 0.0f;

    const float* wscp = g_wsc + b * SEQ;
    const float* wvlp = g_wvl + b * SEQ;

    for (int t = 0; t < NKT; t++) {
        const int slot = t & 1;
        CPA_WAIT0();
        __syncthreads();

        if (t + 1 < NKT)
            KV_ISSUE(slot ^ 1, t + 1);

        const uint32_t kb = sb + KVBASE + (uint32_t)slot * SLOT_B;

        // ---- S = q k^T : fp32-acc fp16 mma ----
        float s[8][4];
#pragma unroll
        for (int j = 0; j < 8; j++)
            s[j][0] = s[j][1] = s[j][2] = s[j][3] = 0.0f;

#pragma unroll
        for (int kk = 0; kk < 4; kk++) {
#pragma unroll
            for (int jp = 0; jp < 4; jp++) {
                const uint32_t off =
                    (uint32_t)((jp * 16 + k_row) * ATS + kk * 16 + k_col) * 2;
                uint32_t kh0, kh1, kh2, kh3;
                LDSM_X4(kh0, kh1, kh2, kh3, kb + OK + off);
                MMA_FP16(s[2 * jp],     qh[kk][0], qh[kk][1], qh[kk][2], qh[kk][3], kh0, kh1);
                MMA_FP16(s[2 * jp + 1], qh[kk][0], qh[kk][1], qh[kk][2], qh[kk][3], kh2, kh3);
            }
        }

        // ---- logit transform (log2 domain) + row max ----
        const int wbase = t * 64;
        float mx0 = -1e30f, mx1 = -1e30f;
#pragma unroll
        for (int j = 0; j < 8; j++) {
            const float2 ws = *(const float2*)&wscp[wbase + j * 8 + 2 * tig];
            const float2 wv = *(const float2*)&wvlp[wbase + j * 8 + 2 * tig];
            s[j][0] = fmaf(s[j][0], ws.x, wv.x);
            s[j][1] = fmaf(s[j][1], ws.y, wv.y);
            s[j][2] = fmaf(s[j][2], ws.x, wv.x);
            s[j][3] = fmaf(s[j][3], ws.y, wv.y);
            mx0 = fmaxf(mx0, fmaxf(s[j][0], s[j][1]));
            mx1 = fmaxf(mx1, fmaxf(s[j][2], s[j][3]));
        }
        mx0 = fmaxf(mx0, __shfl_xor_sync(0xffffffffu, mx0, 1));
        mx0 = fmaxf(mx0, __shfl_xor_sync(0xffffffffu, mx0, 2));
        mx1 = fmaxf(mx1, __shfl_xor_sync(0xffffffffu, mx1, 1));
        mx1 = fmaxf(mx1, __shfl_xor_sync(0xffffffffu, mx1, 2));

        const float mn0 = fmaxf(m0, mx0), mn1 = fmaxf(m1, mx1);
        const float c0 = exp2f(m0 - mn0), c1 = exp2f(m1 - mn1);
        m0 = mn0; m1 = mn1;

        float rs0 = 0.0f, rs1 = 0.0f;
#pragma unroll
        for (int j = 0; j < 8; j++) {
            s[j][0] = exp2f(s[j][0] - m0);
            s[j][1] = exp2f(s[j][1] - m0);
            s[j][2] = exp2f(s[j][2] - m1);
            s[j][3] = exp2f(s[j][3] - m1);
            rs0 += s[j][0] + s[j][1];
            rs1 += s[j][2] + s[j][3];
        }
        rs0 += __shfl_xor_sync(0xffffffffu, rs0, 1);
        rs0 += __shfl_xor_sync(0xffffffffu, rs0, 2);
        rs1 += __shfl_xor_sync(0xffffffffu, rs1, 1);
        rs1 += __shfl_xor_sync(0xffffffffu, rs1, 2);

        l0 = l0 * c0 + rs0;
        l1 = l1 * c1 + rs1;

        // ---- pack P (fp16) for all kk ----
        uint32_t ph[4][4];
#pragma unroll
        for (int kk = 0; kk < 4; kk++) {
            ph[kk][0] = packh2(s[2 * kk][0],     s[2 * kk][1]);
            ph[kk][1] = packh2(s[2 * kk][2],     s[2 * kk][3]);
            ph[kk][2] = packh2(s[2 * kk + 1][0], s[2 * kk + 1][1]);
            ph[kk][3] = packh2(s[2 * kk + 1][2], s[2 * kk + 1][3]);
        }

        // ---- rescale o by correction ----
#pragma unroll
        for (int j = 0; j < 8; j++) {
            o[j][0] *= c0; o[j][1] *= c0;
            o[j][2] *= c1; o[j][3] *= c1;
        }

        // ---- PV tile in fp16 accumulators (4 chained MMAs), promote ----
#pragma unroll
        for (int jp = 0; jp < 4; jp++) {
            uint32_t ta0 = 0, ta1 = 0, tb0 = 0, tb1 = 0;
#pragma unroll
            for (int kk = 0; kk < 4; kk++) {
                const uint32_t off =
                    (uint32_t)((kk * 16 + a_row) * ATS + jp * 16 + a_col) * 2;
                uint32_t vh0, vh1, vh2, vh3;
                LDSM_X4_T(vh0, vh1, vh2, vh3, kb + OV + off);
                MMA_FP16_H(ta0, ta1, ph[kk][0], ph[kk][1], ph[kk][2], ph[kk][3], vh0, vh1);
                MMA_FP16_H(tb0, tb1, ph[kk][0], ph[kk][1], ph[kk][2], ph[kk][3], vh2, vh3);
            }
            // promote: d0 = (row g, cols 2tig,2tig+1), d1 = row g+8
            {
                float2 f;
                f = __half22float2(*reinterpret_cast<__half2*>(&ta0));
                o[2 * jp][0] += f.x;  o[2 * jp][1] += f.y;
                f = __half22float2(*reinterpret_cast<__half2*>(&ta1));
                o[2 * jp][2] += f.x;  o[2 * jp][3] += f.y;
                f = __half22float2(*reinterpret_cast<__half2*>(&tb0));
                o[2 * jp + 1][0] += f.x;  o[2 * jp + 1][1] += f.y;
                f = __half22float2(*reinterpret_cast<__half2*>(&tb1));
                o[2 * jp + 1][2] += f.x;  o[2 * jp + 1][3] += f.y;
            }
        }
    }

    // ---- epilogue ----
    const float i0 = 1.0f / l0, i1 = 1.0f / l1;
    const int grow = b * SEQ + qt * 128 + 16 * wrp + g;
#pragma unroll
    for (int j = 0; j < 8; j++) {
        const int col = h * 64 + j * 8 + 2 * tig;
        *(float2*)(out + (size_t)grow * EMB + col) =
            make_float2(o[j][0] * i0, o[j][1] * i0);
        *(float2*)(out + (size_t)(grow + 8) * EMB + col) =
            make_float2(o[j][2] * i1, o[j][3] * i1);
    }
#undef KV_ISSUE
}

// ---------------------------------------------------------------------------
extern "C" void kernel_launch(void* const* d_in, const int* in_sizes, int n_in,
                              void* d_out, int out_size)
{
    const float* x    = (const float*)d_in[0];
    const float* w    = (const float*)d_in[1];
    const float* Wqkv = (const float*)d_in[2];
    const float* bqkv = (const float*)d_in[3];
    float* out = (float*)d_out;

    cudaFuncSetAttribute(qkv_gemm,
                         cudaFuncAttributeMaxDynamicSharedMemorySize,
                         GEMM_SMEM_BYTES);
    cudaFuncSetAttribute(attn_fp16,
                         cudaFuncAttributeMaxDynamicSharedMemorySize,
                         ATTN_SMEM_BYTES);

    prep_xw_kernel<<<(NX4 + NW4 + 255) / 256, 256>>>((const float4*)x,
                                                     (const float4*)Wqkv);
    wprep_kernel<<<(BATCH * SEQ + 255) / 256, 256>>>(w);

    dim3 g1(QKVN / 128, MROWS / 128);            // (24, 32)
    qkv_gemm<<<g1, 256, GEMM_SMEM_BYTES>>>(bqkv);

    dim3 g2(SEQ / 128, NHEAD, BATCH);            // (16, 16, 2)
    attn_fp16<<<g2, 256, ATTN_SMEM_BYTES>>>(out);
}